// round 8
// baseline (speedup 1.0000x reference)
#include <cuda_runtime.h>
#include <cuda_fp16.h>
#include <cstdint>
#include <math.h>

// ---------------------------------------------------------------------------
// Problem constants
// ---------------------------------------------------------------------------
#define B_   4
#define V_   6
#define C_   256
#define C2_  128          // C/2 packed fp16 pairs
#define HW_  4096
#define NH_  8
#define DH_  32
#define CHW_ (C_ * HW_)

// GEMM tiling
#define MT   128
#define NTT  128
#define KB   32           // k chunk (16 pairs)
#define NKCH (C_ / KB)    // 8

// smem (u32 units): A [m][k2] pitch 20; B [k2][p] pitch 136
#define AP    20
#define A_U   (MT * AP)                   // 2560
#define BPAD  136
#define B_U   (16 * BPAD)                 // 2176
#define BUF_U (2 * A_U + B_U)             // Ah, Al, Bh = 7296
#define NSTG  2
#define SMEM_MMA (NSTG * BUF_U * 4)       // 58368 B -> 3 CTAs/SM fit

// ---------------------------------------------------------------------------
// Scratch (device globals)
// ---------------------------------------------------------------------------
__device__ __align__(128) uint32_t g_xpk_hi [B_ * V_ * C2_ * HW_];  // [(b v)][c2][p]
__device__ __align__(128) uint32_t g_xmpk_hi[B_ * C2_ * HW_];       // [b][c2][p]
__device__ __align__(128) uint32_t g_wpk_hi [4 * C_ * C2_];         // [w][o][c2]
__device__ __align__(128) uint32_t g_wpk_lo [4 * C_ * C2_];
__device__ __align__(128) uint32_t g_apk_hi [B_ * C2_ * HW_];       // attn out packed
__device__ __align__(128) __half  g_qloc[B_ * CHW_];                // fp16
__device__ __align__(128) __half  g_kbuf[B_ * V_ * CHW_];           // fp16
__device__ __align__(128) float   g_vbuf[B_ * V_ * CHW_];           // fp32

// ---------------------------------------------------------------------------
// Helpers
// ---------------------------------------------------------------------------
__device__ __forceinline__ uint32_t smem_u32(const void* p) {
    uint32_t a;
    asm("{ .reg .u64 t; cvta.to.shared.u64 t, %1; cvt.u32.u64 %0, t; }" : "=r"(a) : "l"(p));
    return a;
}
__device__ __forceinline__ uint32_t packhf(float e0, float e1) {
    return ((uint32_t)__half_as_ushort(__float2half_rn(e1)) << 16)
         | (uint32_t)__half_as_ushort(__float2half_rn(e0));
}
__device__ __forceinline__ float hfres(float v) {
    return v - __half2float(__float2half_rn(v));
}
__device__ __forceinline__ void mma16816(float* c, const uint32_t* a,
                                         uint32_t b0, uint32_t b1) {
    asm volatile(
        "mma.sync.aligned.m16n8k16.row.col.f32.f16.f16.f32 "
        "{%0,%1,%2,%3}, {%4,%5,%6,%7}, {%8,%9}, {%0,%1,%2,%3};\n"
        : "+f"(c[0]), "+f"(c[1]), "+f"(c[2]), "+f"(c[3])
        : "r"(a[0]), "r"(a[1]), "r"(a[2]), "r"(a[3]), "r"(b0), "r"(b1));
}
__device__ __forceinline__ void cpasync16(uint32_t dst, const void* src) {
    asm volatile("cp.async.cg.shared.global [%0], [%1], 16;\n" :: "r"(dst), "l"(src));
}
#define CP_COMMIT() asm volatile("cp.async.commit_group;\n" ::: "memory")
#define CP_WAIT(n)  asm volatile("cp.async.wait_group %0;\n" :: "n"(n) : "memory")

// ---------------------------------------------------------------------------
// prep_w: split + pair-pack the four 256x256 weights (fp16 hi/lo). [w][o][c2]
// ---------------------------------------------------------------------------
__global__ void __launch_bounds__(256) prep_w_kernel(
    const float* __restrict__ Wq, const float* __restrict__ Wk,
    const float* __restrict__ Wv, const float* __restrict__ Wo,
    uint32_t* __restrict__ hi, uint32_t* __restrict__ lo)
{
    const int i = blockIdx.x * 256 + threadIdx.x;
    const int w = i >> 15;
    const int r = i & 32767;
    const float* src = (w == 0) ? Wq : (w == 1) ? Wk : (w == 2) ? Wv : Wo;
    const float2 f = *(const float2*)(src + r * 2);
    hi[i] = packhf(f.x, f.y);
    lo[i] = packhf(hfres(f.x), hfres(f.y));
}

// ---------------------------------------------------------------------------
// prep_x: fused view-mean + fp16 pair-pack (hi only).
// grid (HW/1024, C2, B), block 256; thread handles 4 p's.
// ---------------------------------------------------------------------------
__global__ void __launch_bounds__(256) prep_x_kernel(
    const float* __restrict__ x,
    uint32_t* __restrict__ xhi, uint32_t* __restrict__ mhi)
{
    const int p  = blockIdx.x * 1024 + threadIdx.x * 4;
    const int c2 = blockIdx.y;
    const int b  = blockIdx.z;

    float4 se = make_float4(0.f, 0.f, 0.f, 0.f);
    float4 so = make_float4(0.f, 0.f, 0.f, 0.f);
#pragma unroll
    for (int v = 0; v < V_; ++v) {
        const float* base = x + ((size_t)((b * V_ + v) * C_) + c2 * 2) * HW_ + p;
        const float4 e = *(const float4*)base;
        const float4 o = *(const float4*)(base + HW_);
        se.x += e.x; se.y += e.y; se.z += e.z; se.w += e.w;
        so.x += o.x; so.y += o.y; so.z += o.z; so.w += o.w;
        const size_t dst = ((size_t)(b * V_ + v) * C2_ + c2) * HW_ + p;
        *(uint4*)(xhi + dst) = make_uint4(packhf(e.x, o.x), packhf(e.y, o.y),
                                          packhf(e.z, o.z), packhf(e.w, o.w));
    }
    const float inv = 1.0f / 6.0f;
    const size_t dst = ((size_t)b * C2_ + c2) * HW_ + p;
    *(uint4*)(mhi + dst) = make_uint4(
        packhf(se.x * inv, so.x * inv), packhf(se.y * inv, so.y * inv),
        packhf(se.z * inv, so.z * inv), packhf(se.w * inv, so.w * inv));
}

// ---------------------------------------------------------------------------
// HMMA GEMM, fp16 2-product:  Y[z][o][p] = sum_c W[o][c] * X[z][c][p]
//   D = Wh*Xh + Wl*Xh. Double-buffered cp.async, 3 CTAs/SM.
//   KV=1: z in [0,48): view=z>>1, sel=z&1 (sel0 -> fp16 out, sel1 -> fp32).
//   KV=0: E16 selects output type.
// ---------------------------------------------------------------------------
template <int KV, int E16>
__global__ void __launch_bounds__(256, 3) gemm_pk(
    const uint32_t* __restrict__ Wh0, const uint32_t* __restrict__ Wl0,
    const uint32_t* __restrict__ Wh1, const uint32_t* __restrict__ Wl1,
    const uint32_t* __restrict__ Xh,
    void* __restrict__ Y0g, void* __restrict__ Y1g)
{
    extern __shared__ __align__(16) uint32_t smem[];
    const uint32_t sb = smem_u32(smem);

    const uint32_t *Wh, *Wl, *Xhz;
    void* Yv;
    bool f16o;
    if (KV) {
        const int view = blockIdx.z >> 1;
        const int sel = blockIdx.z & 1;
        Wh = sel ? Wh1 : Wh0;
        Wl = sel ? Wl1 : Wl0;
        Xhz = Xh + (size_t)view * C2_ * HW_;
        f16o = (sel == 0);
        Yv = sel ? (void*)((float*)Y1g + (size_t)view * CHW_)
                 : (void*)((__half*)Y0g + (size_t)view * CHW_);
    } else {
        Wh = Wh0; Wl = Wl0;
        Xhz = Xh + (size_t)blockIdx.z * C2_ * HW_;
        f16o = (E16 != 0);
        Yv = E16 ? (void*)((__half*)Y0g + (size_t)blockIdx.z * CHW_)
                 : (void*)((float*)Y0g + (size_t)blockIdx.z * CHW_);
    }

    const int tid = threadIdx.x;
    const int lane = tid & 31;
    const int wid = tid >> 5;
    const int p0 = blockIdx.x * NTT;
    const int o0 = blockIdx.y * MT;

    // async-copy indices
    const int a_o  = tid >> 2;          // 0..63 (+64)
    const int a_k4 = (tid & 3) * 4;
    const int b_r  = tid >> 5;          // 0..7 (+8)
    const int b_p4 = (tid & 31) * 4;

    // mma fragment indices
    const int g = lane >> 2;
    const int t = lane & 3;
    const int mwb = (wid & 3) * 32;
    const int nwb = (wid >> 2) * 64;

    float acc[2][8][4];
#pragma unroll
    for (int mi = 0; mi < 2; ++mi)
#pragma unroll
        for (int ni = 0; ni < 8; ++ni)
#pragma unroll
            for (int j = 0; j < 4; ++j) acc[mi][ni][j] = 0.f;

    auto issue = [&](int kc, int buf) {
        const uint32_t base = sb + buf * BUF_U * 4;
        const uint32_t dAh = base;
        const uint32_t dAl = base + A_U * 4;
        const uint32_t dBh = base + 2 * A_U * 4;
#pragma unroll
        for (int r = 0; r < 2; ++r) {
            const int o = a_o + r * 64;
            const size_t wsrc = (size_t)(o0 + o) * C2_ + kc * 16 + a_k4;
            const uint32_t wdst = (o * AP + a_k4) * 4;
            cpasync16(dAh + wdst, Wh + wsrc);
            cpasync16(dAl + wdst, Wl + wsrc);
            const int row = b_r + r * 8;
            const size_t xsrc = (size_t)(kc * 16 + row) * HW_ + p0 + b_p4;
            cpasync16(dBh + (row * BPAD + b_p4) * 4, Xhz + xsrc);
        }
        CP_COMMIT();
    };

    issue(0, 0);

    for (int kc = 0; kc < NKCH; ++kc) {
        if (kc + 1 < NKCH) {
            issue(kc + 1, (kc + 1) & 1);
            CP_WAIT(1);
        } else {
            CP_WAIT(0);
        }
        __syncthreads();

        const uint32_t* bb = smem + (kc & 1) * BUF_U;
        const uint32_t* sAh = bb;
        const uint32_t* sAl = bb + A_U;
        const uint32_t* sBh = bb + 2 * A_U;

#pragma unroll
        for (int s = 0; s < 2; ++s) {
            const int k2r0 = s * 8 + t;
            const int k2r1 = s * 8 + t + 4;
#pragma unroll
            for (int pr = 0; pr < 2; ++pr) {      // product: hi then lo
                const uint32_t* sA = pr ? sAl : sAh;
                uint32_t a[2][4];
#pragma unroll
                for (int mi = 0; mi < 2; ++mi) {
                    const int m0 = mwb + mi * 16 + g;
                    a[mi][0] = sA[m0 * AP + k2r0];
                    a[mi][1] = sA[(m0 + 8) * AP + k2r0];
                    a[mi][2] = sA[m0 * AP + k2r1];
                    a[mi][3] = sA[(m0 + 8) * AP + k2r1];
                }
#pragma unroll
                for (int ni = 0; ni < 8; ++ni) {
                    const int n0 = nwb + ni * 8 + g;
                    const uint32_t b0 = sBh[k2r0 * BPAD + n0];
                    const uint32_t b1 = sBh[k2r1 * BPAD + n0];
                    mma16816(acc[0][ni], a[0], b0, b1);
                    mma16816(acc[1][ni], a[1], b0, b1);
                }
            }
        }
        __syncthreads();
    }

    // epilogue
    if (f16o) {
        __half* Yh = (__half*)Yv;
#pragma unroll
        for (int mi = 0; mi < 2; ++mi) {
            const int o = o0 + mwb + mi * 16 + g;
#pragma unroll
            for (int ni = 0; ni < 8; ++ni) {
                const int p = p0 + nwb + ni * 8 + t * 2;
                *(__half2*)(Yh + (size_t)o * HW_ + p) =
                    __floats2half2_rn(acc[mi][ni][0], acc[mi][ni][1]);
                *(__half2*)(Yh + (size_t)(o + 8) * HW_ + p) =
                    __floats2half2_rn(acc[mi][ni][2], acc[mi][ni][3]);
            }
        }
    } else {
        float* Y = (float*)Yv;
#pragma unroll
        for (int mi = 0; mi < 2; ++mi) {
            const int o = o0 + mwb + mi * 16 + g;
#pragma unroll
            for (int ni = 0; ni < 8; ++ni) {
                const int p = p0 + nwb + ni * 8 + t * 2;
                *(float2*)(Y + (size_t)o * HW_ + p) =
                    make_float2(acc[mi][ni][0], acc[mi][ni][1]);
                *(float2*)(Y + (size_t)(o + 8) * HW_ + p) =
                    make_float2(acc[mi][ni][2], acc[mi][ni][3]);
            }
        }
    }
}

// ---------------------------------------------------------------------------
// Per-pixel cross-view attention. Q,K fp16; V fp32. Emits packed fp16 out.
// ---------------------------------------------------------------------------
__global__ void __launch_bounds__(256) attn_kernel(
    const __half* __restrict__ Q, const __half* __restrict__ K,
    const float* __restrict__ Vv, uint32_t* __restrict__ Ohi)
{
    const int p = ((blockIdx.x & 15) << 8) + threadIdx.x;
    const int bh = blockIdx.x >> 4;
    const int b = bh >> 3;
    const int h = bh & 7;

    const size_t qbase = ((size_t)(b * C_ + h * DH_)) * HW_ + p;

    float q[DH_];
#pragma unroll
    for (int d = 0; d < DH_; ++d) q[d] = __half2float(Q[qbase + (size_t)d * HW_]);

    float s[V_];
#pragma unroll
    for (int v = 0; v < V_; ++v) {
        const size_t kb = ((size_t)((b * V_ + v) * C_ + h * DH_)) * HW_ + p;
        float dot = 0.f;
#pragma unroll
        for (int d = 0; d < DH_; ++d)
            dot += q[d] * __half2float(K[kb + (size_t)d * HW_]);
        s[v] = dot * 0.17677669529663687f;
    }
    float m = s[0];
#pragma unroll
    for (int v = 1; v < V_; ++v) m = fmaxf(m, s[v]);
    float sum = 0.f;
#pragma unroll
    for (int v = 0; v < V_; ++v) { s[v] = expf(s[v] - m); sum += s[v]; }
    const float invsum = 1.f / sum;

    float acc[DH_];
#pragma unroll
    for (int d = 0; d < DH_; ++d) acc[d] = 0.f;
#pragma unroll
    for (int v = 0; v < V_; ++v) {
        const float w = s[v] * invsum;
        const size_t vb = ((size_t)((b * V_ + v) * C_ + h * DH_)) * HW_ + p;
#pragma unroll
        for (int d = 0; d < DH_; ++d) acc[d] += w * Vv[vb + (size_t)d * HW_];
    }
    const size_t obase = ((size_t)(b * C2_ + h * (DH_ / 2))) * HW_ + p;
#pragma unroll
    for (int d2 = 0; d2 < DH_ / 2; ++d2)
        Ohi[obase + (size_t)d2 * HW_] = packhf(acc[d2 * 2], acc[d2 * 2 + 1]);
}

// ---------------------------------------------------------------------------
// kernel_launch
// ---------------------------------------------------------------------------
extern "C" void kernel_launch(void* const* d_in, const int* in_sizes, int n_in,
                              void* d_out, int out_size)
{
    const float* x  = (const float*)d_in[0];
    const float* Wq = (const float*)d_in[1];
    const float* Wk = (const float*)d_in[2];
    const float* Wv = (const float*)d_in[3];
    const float* Wo = (const float*)d_in[4];
    float* out = (float*)d_out;

    void* p;
    cudaGetSymbolAddress(&p, g_xpk_hi);  uint32_t* xhi = (uint32_t*)p;
    cudaGetSymbolAddress(&p, g_xmpk_hi); uint32_t* mhi = (uint32_t*)p;
    cudaGetSymbolAddress(&p, g_wpk_hi);  uint32_t* whi = (uint32_t*)p;
    cudaGetSymbolAddress(&p, g_wpk_lo);  uint32_t* wlo = (uint32_t*)p;
    cudaGetSymbolAddress(&p, g_apk_hi);  uint32_t* ahi = (uint32_t*)p;
    cudaGetSymbolAddress(&p, g_qloc);    __half* qloc = (__half*)p;
    cudaGetSymbolAddress(&p, g_kbuf);    __half* kbuf = (__half*)p;
    cudaGetSymbolAddress(&p, g_vbuf);    float*  vbuf = (float*)p;

    cudaFuncSetAttribute(gemm_pk<0,0>, cudaFuncAttributeMaxDynamicSharedMemorySize, SMEM_MMA);
    cudaFuncSetAttribute(gemm_pk<0,1>, cudaFuncAttributeMaxDynamicSharedMemorySize, SMEM_MMA);
    cudaFuncSetAttribute(gemm_pk<1,1>, cudaFuncAttributeMaxDynamicSharedMemorySize, SMEM_MMA);

    const int WSZ = C_ * C2_;

    prep_w_kernel<<<4 * WSZ / 256, 256>>>(Wq, Wk, Wv, Wo, whi, wlo);
    {
        dim3 g(HW_ / 1024, C2_, B_);
        prep_x_kernel<<<g, 256>>>(x, xhi, mhi);
    }
    {   // Qloc = Wq * xmean  -> fp16
        dim3 g(HW_ / NTT, C_ / MT, B_);
        gemm_pk<0,1><<<g, 256, SMEM_MMA>>>(whi + 0 * WSZ, wlo + 0 * WSZ,
                                           nullptr, nullptr, mhi, qloc, nullptr);
    }
    {   // K (fp16) and V (fp32) projections
        dim3 g(HW_ / NTT, C_ / MT, B_ * V_ * 2);
        gemm_pk<1,1><<<g, 256, SMEM_MMA>>>(whi + 1 * WSZ, wlo + 1 * WSZ,
                                           whi + 2 * WSZ, wlo + 2 * WSZ,
                                           xhi, kbuf, vbuf);
    }
    attn_kernel<<<B_ * NH_ * (HW_ / 256), 256>>>(qloc, kbuf, vbuf, ahi);
    {   // out = Wo * att  -> fp32
        dim3 g(HW_ / NTT, C_ / MT, B_);
        gemm_pk<0,0><<<g, 256, SMEM_MMA>>>(whi + 3 * WSZ, wlo + 3 * WSZ,
                                           nullptr, nullptr, ahi, out, nullptr);
    }
}

// round 9
// speedup vs baseline: 1.9690x; 1.9690x over previous
#include <cuda_runtime.h>
#include <cuda_fp16.h>
#include <cstdint>
#include <math.h>

// ---------------------------------------------------------------------------
// Problem constants
// ---------------------------------------------------------------------------
#define B_   4
#define V_   6
#define C_   256
#define C2_  128          // C/2 packed fp16 pairs
#define HW_  4096
#define NH_  8
#define DH_  32
#define CHW_ (C_ * HW_)

// GEMM tiling
#define MT   128
#define NTT  128
#define KB   32           // k chunk (16 pairs)
#define NKCH (C_ / KB)    // 8

// smem (u32 units):
//   A fragment-ordered: [blk(8)][s(2)][lane(32)][4] = 2048 u32 per matrix
//   B [k2(16)][p(128)] pitch 136
#define A_U   2048
#define BPAD  136
#define B_U   (16 * BPAD)                 // 2176
#define BUF_U (2 * A_U + B_U)             // Ah, Al, Bh = 6272
#define NSTG  3
#define SMEM_MMA (NSTG * BUF_U * 4)       // 75264 B (2 CTAs/SM)

// ---------------------------------------------------------------------------
// Scratch (device globals)
// ---------------------------------------------------------------------------
__device__ __align__(128) uint32_t g_xpk_hi [B_ * V_ * C2_ * HW_];  // [(b v)][c2][p]
__device__ __align__(128) uint32_t g_xmpk_hi[B_ * C2_ * HW_];       // [b][c2][p]
__device__ __align__(128) uint32_t g_wpk_hi [4 * C_ * C2_];         // fragment order
__device__ __align__(128) uint32_t g_wpk_lo [4 * C_ * C2_];
__device__ __align__(128) uint32_t g_apk_hi [B_ * C2_ * HW_];       // attn out packed
__device__ __align__(128) __half  g_qloc[B_ * CHW_];                // fp16
__device__ __align__(128) __half  g_kbuf[B_ * V_ * CHW_];           // fp16
__device__ __align__(128) float   g_vbuf[B_ * V_ * CHW_];           // fp32

// ---------------------------------------------------------------------------
// Helpers
// ---------------------------------------------------------------------------
__device__ __forceinline__ uint32_t smem_u32(const void* p) {
    uint32_t a;
    asm("{ .reg .u64 t; cvta.to.shared.u64 t, %1; cvt.u32.u64 %0, t; }" : "=r"(a) : "l"(p));
    return a;
}
__device__ __forceinline__ uint32_t packhf(float e0, float e1) {
    return ((uint32_t)__half_as_ushort(__float2half_rn(e1)) << 16)
         | (uint32_t)__half_as_ushort(__float2half_rn(e0));
}
__device__ __forceinline__ float hfres(float v) {
    return v - __half2float(__float2half_rn(v));
}
__device__ __forceinline__ void mma16816(float* c, const uint32_t* a,
                                         uint32_t b0, uint32_t b1) {
    asm volatile(
        "mma.sync.aligned.m16n8k16.row.col.f32.f16.f16.f32 "
        "{%0,%1,%2,%3}, {%4,%5,%6,%7}, {%8,%9}, {%0,%1,%2,%3};\n"
        : "+f"(c[0]), "+f"(c[1]), "+f"(c[2]), "+f"(c[3])
        : "r"(a[0]), "r"(a[1]), "r"(a[2]), "r"(a[3]), "r"(b0), "r"(b1));
}
__device__ __forceinline__ void cpasync16(uint32_t dst, const void* src) {
    asm volatile("cp.async.cg.shared.global [%0], [%1], 16;\n" :: "r"(dst), "l"(src));
}
#define CP_COMMIT() asm volatile("cp.async.commit_group;\n" ::: "memory")
#define CP_WAIT(n)  asm volatile("cp.async.wait_group %0;\n" :: "n"(n) : "memory")

// ---------------------------------------------------------------------------
// prep_w: split + pair-pack weights into MMA FRAGMENT ORDER.
//   Output index (within one weight): [ot(2)][kc(8)][blk(8)][s(2)][lane(32)][j(4)]
//   j: o = ot*128 + blk*16 + (j&1)*8 + (lane>>2)
//      k2 = kc*16 + s*8 + (j>>1)*4 + (lane&3)
// ---------------------------------------------------------------------------
__global__ void __launch_bounds__(256) prep_w_kernel(
    const float* __restrict__ Wq, const float* __restrict__ Wk,
    const float* __restrict__ Wv, const float* __restrict__ Wo,
    uint32_t* __restrict__ hi, uint32_t* __restrict__ lo)
{
    const int i = blockIdx.x * 256 + threadIdx.x;   // 0 .. 4*32768
    const int w = i >> 15;
    const int r = i & 32767;
    const int j    = r & 3;
    const int lane = (r >> 2) & 31;
    const int s    = (r >> 7) & 1;
    const int blk  = (r >> 8) & 7;
    const int kc   = (r >> 11) & 7;
    const int ot   = (r >> 14) & 1;
    const int o  = ot * 128 + blk * 16 + (j & 1) * 8 + (lane >> 2);
    const int k2 = kc * 16 + s * 8 + (j >> 1) * 4 + (lane & 3);
    const float* src = (w == 0) ? Wq : (w == 1) ? Wk : (w == 2) ? Wv : Wo;
    const float2 f = *(const float2*)(src + o * C_ + k2 * 2);
    hi[i] = packhf(f.x, f.y);
    lo[i] = packhf(hfres(f.x), hfres(f.y));
}

// ---------------------------------------------------------------------------
// prep_x: fused view-mean + fp16 pair-pack (hi only). [c2][p] layout.
// ---------------------------------------------------------------------------
__global__ void __launch_bounds__(256) prep_x_kernel(
    const float* __restrict__ x,
    uint32_t* __restrict__ xhi, uint32_t* __restrict__ mhi)
{
    const int p  = blockIdx.x * 1024 + threadIdx.x * 4;
    const int c2 = blockIdx.y;
    const int b  = blockIdx.z;

    float4 se = make_float4(0.f, 0.f, 0.f, 0.f);
    float4 so = make_float4(0.f, 0.f, 0.f, 0.f);
#pragma unroll
    for (int v = 0; v < V_; ++v) {
        const float* base = x + ((size_t)((b * V_ + v) * C_) + c2 * 2) * HW_ + p;
        const float4 e = *(const float4*)base;
        const float4 o = *(const float4*)(base + HW_);
        se.x += e.x; se.y += e.y; se.z += e.z; se.w += e.w;
        so.x += o.x; so.y += o.y; so.z += o.z; so.w += o.w;
        const size_t dst = ((size_t)(b * V_ + v) * C2_ + c2) * HW_ + p;
        *(uint4*)(xhi + dst) = make_uint4(packhf(e.x, o.x), packhf(e.y, o.y),
                                          packhf(e.z, o.z), packhf(e.w, o.w));
    }
    const float inv = 1.0f / 6.0f;
    const size_t dst = ((size_t)b * C2_ + c2) * HW_ + p;
    *(uint4*)(mhi + dst) = make_uint4(
        packhf(se.x * inv, so.x * inv), packhf(se.y * inv, so.y * inv),
        packhf(se.z * inv, so.z * inv), packhf(se.w * inv, so.w * inv));
}

// ---------------------------------------------------------------------------
// HMMA GEMM, fp16 2-product, fragment-ordered A (LDS.128), R6 pipeline.
//   Y[z][o][p] = sum_c W[o][c] * X[z][c][p];  D = Wh*Xh + Wl*Xh.
// ---------------------------------------------------------------------------
template <int KV, int E16>
__global__ void __launch_bounds__(256) gemm_pk(
    const uint32_t* __restrict__ Wh0, const uint32_t* __restrict__ Wl0,
    const uint32_t* __restrict__ Wh1, const uint32_t* __restrict__ Wl1,
    const uint32_t* __restrict__ Xh,
    void* __restrict__ Y0g, void* __restrict__ Y1g)
{
    extern __shared__ __align__(128) uint32_t smem[];
    const uint32_t sb = smem_u32(smem);

    const uint32_t *Wh, *Wl, *Xhz;
    void* Yv;
    bool f16o;
    if (KV) {
        const int view = blockIdx.z >> 1;
        const int sel = blockIdx.z & 1;
        Wh = sel ? Wh1 : Wh0;
        Wl = sel ? Wl1 : Wl0;
        Xhz = Xh + (size_t)view * C2_ * HW_;
        f16o = (sel == 0);
        Yv = sel ? (void*)((float*)Y1g + (size_t)view * CHW_)
                 : (void*)((__half*)Y0g + (size_t)view * CHW_);
    } else {
        Wh = Wh0; Wl = Wl0;
        Xhz = Xh + (size_t)blockIdx.z * C2_ * HW_;
        f16o = (E16 != 0);
        Yv = E16 ? (void*)((__half*)Y0g + (size_t)blockIdx.z * CHW_)
                 : (void*)((float*)Y0g + (size_t)blockIdx.z * CHW_);
    }

    const int tid = threadIdx.x;
    const int lane = tid & 31;
    const int wid = tid >> 5;
    const int p0 = blockIdx.x * NTT;
    const int ot = blockIdx.y;              // o tile (o0 = ot*128)
    const int o0 = ot * MT;

    // cp.async B indices
    const int b_r  = tid >> 5;          // 0..7 (+8)
    const int b_p4 = (tid & 31) * 4;

    // mma fragment indices
    const int g = lane >> 2;
    const int t = lane & 3;
    const int mwb = (wid & 3) * 32;
    const int nwb = (wid >> 2) * 64;
    const int blk0 = (wid & 3) * 2;     // fragment block for mi=0

    float acc[2][8][4];
#pragma unroll
    for (int mi = 0; mi < 2; ++mi)
#pragma unroll
        for (int ni = 0; ni < 8; ++ni)
#pragma unroll
            for (int j = 0; j < 4; ++j) acc[mi][ni][j] = 0.f;

    auto issue = [&](int kc, int buf) {
        const uint32_t base = sb + buf * BUF_U * 4;
        const uint32_t dAh = base;
        const uint32_t dAl = base + A_U * 4;
        const uint32_t dBh = base + 2 * A_U * 4;
        const size_t wsrc = (size_t)(ot * 8 + kc) * A_U;   // fragment-ordered
#pragma unroll
        for (int r = 0; r < 2; ++r) {
            const uint32_t aoff = r * 1024 + tid * 4;      // u32 units
            cpasync16(dAh + aoff * 4, Wh + wsrc + aoff);
            cpasync16(dAl + aoff * 4, Wl + wsrc + aoff);
            const int row = b_r + r * 8;
            const size_t xsrc = (size_t)(kc * 16 + row) * HW_ + p0 + b_p4;
            cpasync16(dBh + (row * BPAD + b_p4) * 4, Xhz + xsrc);
        }
        CP_COMMIT();
    };

    issue(0, 0);
    issue(1, 1);

    for (int kc = 0; kc < NKCH; ++kc) {
        if (kc == NKCH - 1) CP_WAIT(0); else CP_WAIT(1);
        __syncthreads();
        if (kc + 2 < NKCH) issue(kc + 2, (kc + 2) % NSTG);

        const uint32_t* bb = smem + (kc % NSTG) * BUF_U;
        const uint32_t* sAh = bb;
        const uint32_t* sAl = bb + A_U;
        const uint32_t* sBh = bb + 2 * A_U;

#pragma unroll
        for (int s = 0; s < 2; ++s) {
            const int k2r0 = s * 8 + t;
            const int k2r1 = s * 8 + t + 4;
            uint4 ah[2], al[2];
#pragma unroll
            for (int mi = 0; mi < 2; ++mi) {
                const uint32_t fo = (((blk0 + mi) * 2 + s) * 32 + lane) * 4;
                ah[mi] = *(const uint4*)&sAh[fo];
                al[mi] = *(const uint4*)&sAl[fo];
            }
#pragma unroll
            for (int ni = 0; ni < 8; ++ni) {
                const int n0 = nwb + ni * 8 + g;
                const uint32_t b0 = sBh[k2r0 * BPAD + n0];
                const uint32_t b1 = sBh[k2r1 * BPAD + n0];
                mma16816(acc[0][ni], (const uint32_t*)&ah[0], b0, b1);
                mma16816(acc[1][ni], (const uint32_t*)&ah[1], b0, b1);
                mma16816(acc[0][ni], (const uint32_t*)&al[0], b0, b1);
                mma16816(acc[1][ni], (const uint32_t*)&al[1], b0, b1);
            }
        }
        __syncthreads();
    }

    // epilogue
    if (f16o) {
        __half* Yh = (__half*)Yv;
#pragma unroll
        for (int mi = 0; mi < 2; ++mi) {
            const int o = o0 + mwb + mi * 16 + g;
#pragma unroll
            for (int ni = 0; ni < 8; ++ni) {
                const int p = p0 + nwb + ni * 8 + t * 2;
                *(__half2*)(Yh + (size_t)o * HW_ + p) =
                    __floats2half2_rn(acc[mi][ni][0], acc[mi][ni][1]);
                *(__half2*)(Yh + (size_t)(o + 8) * HW_ + p) =
                    __floats2half2_rn(acc[mi][ni][2], acc[mi][ni][3]);
            }
        }
    } else {
        float* Y = (float*)Yv;
#pragma unroll
        for (int mi = 0; mi < 2; ++mi) {
            const int o = o0 + mwb + mi * 16 + g;
#pragma unroll
            for (int ni = 0; ni < 8; ++ni) {
                const int p = p0 + nwb + ni * 8 + t * 2;
                *(float2*)(Y + (size_t)o * HW_ + p) =
                    make_float2(acc[mi][ni][0], acc[mi][ni][1]);
                *(float2*)(Y + (size_t)(o + 8) * HW_ + p) =
                    make_float2(acc[mi][ni][2], acc[mi][ni][3]);
            }
        }
    }
}

// ---------------------------------------------------------------------------
// Per-pixel cross-view attention. Q,K fp16; V fp32. Emits packed fp16 out.
// ---------------------------------------------------------------------------
__global__ void __launch_bounds__(256) attn_kernel(
    const __half* __restrict__ Q, const __half* __restrict__ K,
    const float* __restrict__ Vv, uint32_t* __restrict__ Ohi)
{
    const int p = ((blockIdx.x & 15) << 8) + threadIdx.x;
    const int bh = blockIdx.x >> 4;
    const int b = bh >> 3;
    const int h = bh & 7;

    const size_t qbase = ((size_t)(b * C_ + h * DH_)) * HW_ + p;

    float q[DH_];
#pragma unroll
    for (int d = 0; d < DH_; ++d) q[d] = __half2float(Q[qbase + (size_t)d * HW_]);

    float s[V_];
#pragma unroll
    for (int v = 0; v < V_; ++v) {
        const size_t kb = ((size_t)((b * V_ + v) * C_ + h * DH_)) * HW_ + p;
        float dot = 0.f;
#pragma unroll
        for (int d = 0; d < DH_; ++d)
            dot += q[d] * __half2float(K[kb + (size_t)d * HW_]);
        s[v] = dot * 0.17677669529663687f;
    }
    float m = s[0];
#pragma unroll
    for (int v = 1; v < V_; ++v) m = fmaxf(m, s[v]);
    float sum = 0.f;
#pragma unroll
    for (int v = 0; v < V_; ++v) { s[v] = expf(s[v] - m); sum += s[v]; }
    const float invsum = 1.f / sum;

    float acc[DH_];
#pragma unroll
    for (int d = 0; d < DH_; ++d) acc[d] = 0.f;
#pragma unroll
    for (int v = 0; v < V_; ++v) {
        const float w = s[v] * invsum;
        const size_t vb = ((size_t)((b * V_ + v) * C_ + h * DH_)) * HW_ + p;
#pragma unroll
        for (int d = 0; d < DH_; ++d) acc[d] += w * Vv[vb + (size_t)d * HW_];
    }
    const size_t obase = ((size_t)(b * C2_ + h * (DH_ / 2))) * HW_ + p;
#pragma unroll
    for (int d2 = 0; d2 < DH_ / 2; ++d2)
        Ohi[obase + (size_t)d2 * HW_] = packhf(acc[d2 * 2], acc[d2 * 2 + 1]);
}

// ---------------------------------------------------------------------------
// kernel_launch
// ---------------------------------------------------------------------------
extern "C" void kernel_launch(void* const* d_in, const int* in_sizes, int n_in,
                              void* d_out, int out_size)
{
    const float* x  = (const float*)d_in[0];
    const float* Wq = (const float*)d_in[1];
    const float* Wk = (const float*)d_in[2];
    const float* Wv = (const float*)d_in[3];
    const float* Wo = (const float*)d_in[4];
    float* out = (float*)d_out;

    void* p;
    cudaGetSymbolAddress(&p, g_xpk_hi);  uint32_t* xhi = (uint32_t*)p;
    cudaGetSymbolAddress(&p, g_xmpk_hi); uint32_t* mhi = (uint32_t*)p;
    cudaGetSymbolAddress(&p, g_wpk_hi);  uint32_t* whi = (uint32_t*)p;
    cudaGetSymbolAddress(&p, g_wpk_lo);  uint32_t* wlo = (uint32_t*)p;
    cudaGetSymbolAddress(&p, g_apk_hi);  uint32_t* ahi = (uint32_t*)p;
    cudaGetSymbolAddress(&p, g_qloc);    __half* qloc = (__half*)p;
    cudaGetSymbolAddress(&p, g_kbuf);    __half* kbuf = (__half*)p;
    cudaGetSymbolAddress(&p, g_vbuf);    float*  vbuf = (float*)p;

    cudaFuncSetAttribute(gemm_pk<0,0>, cudaFuncAttributeMaxDynamicSharedMemorySize, SMEM_MMA);
    cudaFuncSetAttribute(gemm_pk<0,1>, cudaFuncAttributeMaxDynamicSharedMemorySize, SMEM_MMA);
    cudaFuncSetAttribute(gemm_pk<1,1>, cudaFuncAttributeMaxDynamicSharedMemorySize, SMEM_MMA);

    const int WSZ = C_ * C2_;

    prep_w_kernel<<<4 * WSZ / 256, 256>>>(Wq, Wk, Wv, Wo, whi, wlo);
    {
        dim3 g(HW_ / 1024, C2_, B_);
        prep_x_kernel<<<g, 256>>>(x, xhi, mhi);
    }
    {   // Qloc = Wq * xmean  -> fp16
        dim3 g(HW_ / NTT, C_ / MT, B_);
        gemm_pk<0,1><<<g, 256, SMEM_MMA>>>(whi + 0 * WSZ, wlo + 0 * WSZ,
                                           nullptr, nullptr, mhi, qloc, nullptr);
    }
    {   // K (fp16) and V (fp32) projections
        dim3 g(HW_ / NTT, C_ / MT, B_ * V_ * 2);
        gemm_pk<1,1><<<g, 256, SMEM_MMA>>>(whi + 1 * WSZ, wlo + 1 * WSZ,
                                           whi + 2 * WSZ, wlo + 2 * WSZ,
                                           xhi, kbuf, vbuf);
    }
    attn_kernel<<<B_ * NH_ * (HW_ / 256), 256>>>(qloc, kbuf, vbuf, ahi);
    {   // out = Wo * att  -> fp32
        dim3 g(HW_ / NTT, C_ / MT, B_);
        gemm_pk<0,0><<<g, 256, SMEM_MMA>>>(whi + 3 * WSZ, wlo + 3 * WSZ,
                                           nullptr, nullptr, ahi, out, nullptr);
    }
}

// round 10
// speedup vs baseline: 2.0154x; 1.0235x over previous
#include <cuda_runtime.h>
#include <cuda_fp16.h>
#include <cstdint>
#include <math.h>

// ---------------------------------------------------------------------------
// Problem constants
// ---------------------------------------------------------------------------
#define B_   4
#define V_   6
#define C_   256
#define C2_  128          // C/2 packed fp16 pairs
#define HW_  4096
#define NH_  8
#define DH_  32
#define CHW_ (C_ * HW_)

// GEMM tiling
#define MT   128
#define NTT  128
#define KB   32           // k chunk (16 pairs)
#define NKCH (C_ / KB)    // 8

// smem (u32 units):
//   A fragment-ordered: [blk(8)][s(2)][lane(32)][4] = 2048 u32 per matrix
//   B [k2(16)][p(128)] pitch 136
#define A_U   2048
#define BPAD  136
#define B_U   (16 * BPAD)                 // 2176
#define BUF_U (2 * A_U + B_U)             // Ah, Al, Bh = 6272
#define NSTG  4
#define SMEM_MMA (NSTG * BUF_U * 4)       // 100352 B (2 CTAs/SM)

// ---------------------------------------------------------------------------
// Scratch (device globals)
// ---------------------------------------------------------------------------
__device__ __align__(128) uint32_t g_xpk_hi [B_ * V_ * C2_ * HW_];  // [(b v)][c2][p]
__device__ __align__(128) uint32_t g_xmpk_hi[B_ * C2_ * HW_];       // [b][c2][p]
__device__ __align__(128) uint32_t g_wpk_hi [4 * C_ * C2_];         // fragment order
__device__ __align__(128) uint32_t g_wpk_lo [4 * C_ * C2_];
__device__ __align__(128) uint32_t g_apk_hi [B_ * C2_ * HW_];       // attn out packed
__device__ __align__(128) __half  g_qloc[B_ * CHW_];                // fp16
__device__ __align__(128) __half  g_kbuf[B_ * V_ * CHW_];           // fp16
__device__ __align__(128) float   g_vbuf[B_ * V_ * CHW_];           // fp32

// ---------------------------------------------------------------------------
// Helpers
// ---------------------------------------------------------------------------
__device__ __forceinline__ uint32_t smem_u32(const void* p) {
    uint32_t a;
    asm("{ .reg .u64 t; cvta.to.shared.u64 t, %1; cvt.u32.u64 %0, t; }" : "=r"(a) : "l"(p));
    return a;
}
__device__ __forceinline__ uint32_t packhf(float e0, float e1) {
    return ((uint32_t)__half_as_ushort(__float2half_rn(e1)) << 16)
         | (uint32_t)__half_as_ushort(__float2half_rn(e0));
}
__device__ __forceinline__ float hfres(float v) {
    return v - __half2float(__float2half_rn(v));
}
__device__ __forceinline__ void mma16816(float* c, const uint32_t* a,
                                         uint32_t b0, uint32_t b1) {
    asm volatile(
        "mma.sync.aligned.m16n8k16.row.col.f32.f16.f16.f32 "
        "{%0,%1,%2,%3}, {%4,%5,%6,%7}, {%8,%9}, {%0,%1,%2,%3};\n"
        : "+f"(c[0]), "+f"(c[1]), "+f"(c[2]), "+f"(c[3])
        : "r"(a[0]), "r"(a[1]), "r"(a[2]), "r"(a[3]), "r"(b0), "r"(b1));
}
__device__ __forceinline__ void cpasync16(uint32_t dst, const void* src) {
    asm volatile("cp.async.cg.shared.global [%0], [%1], 16;\n" :: "r"(dst), "l"(src));
}
#define CP_COMMIT() asm volatile("cp.async.commit_group;\n" ::: "memory")
#define CP_WAIT(n)  asm volatile("cp.async.wait_group %0;\n" :: "n"(n) : "memory")

// ---------------------------------------------------------------------------
// prep_w: split + pair-pack weights into MMA FRAGMENT ORDER.
//   Output index (within one weight): [ot(2)][kc(8)][blk(8)][s(2)][lane(32)][j(4)]
//   j: o = ot*128 + blk*16 + (j&1)*8 + (lane>>2)
//      k2 = kc*16 + s*8 + (j>>1)*4 + (lane&3)
// ---------------------------------------------------------------------------
__global__ void __launch_bounds__(256) prep_w_kernel(
    const float* __restrict__ Wq, const float* __restrict__ Wk,
    const float* __restrict__ Wv, const float* __restrict__ Wo,
    uint32_t* __restrict__ hi, uint32_t* __restrict__ lo)
{
    const int i = blockIdx.x * 256 + threadIdx.x;   // 0 .. 4*32768
    const int w = i >> 15;
    const int r = i & 32767;
    const int j    = r & 3;
    const int lane = (r >> 2) & 31;
    const int s    = (r >> 7) & 1;
    const int blk  = (r >> 8) & 7;
    const int kc   = (r >> 11) & 7;
    const int ot   = (r >> 14) & 1;
    const int o  = ot * 128 + blk * 16 + (j & 1) * 8 + (lane >> 2);
    const int k2 = kc * 16 + s * 8 + (j >> 1) * 4 + (lane & 3);
    const float* src = (w == 0) ? Wq : (w == 1) ? Wk : (w == 2) ? Wv : Wo;
    const float2 f = *(const float2*)(src + o * C_ + k2 * 2);
    hi[i] = packhf(f.x, f.y);
    lo[i] = packhf(hfres(f.x), hfres(f.y));
}

// ---------------------------------------------------------------------------
// prep_x: fused view-mean + fp16 pair-pack (hi only). [c2][p] layout.
// ---------------------------------------------------------------------------
__global__ void __launch_bounds__(256) prep_x_kernel(
    const float* __restrict__ x,
    uint32_t* __restrict__ xhi, uint32_t* __restrict__ mhi)
{
    const int p  = blockIdx.x * 1024 + threadIdx.x * 4;
    const int c2 = blockIdx.y;
    const int b  = blockIdx.z;

    float4 se = make_float4(0.f, 0.f, 0.f, 0.f);
    float4 so = make_float4(0.f, 0.f, 0.f, 0.f);
#pragma unroll
    for (int v = 0; v < V_; ++v) {
        const float* base = x + ((size_t)((b * V_ + v) * C_) + c2 * 2) * HW_ + p;
        const float4 e = *(const float4*)base;
        const float4 o = *(const float4*)(base + HW_);
        se.x += e.x; se.y += e.y; se.z += e.z; se.w += e.w;
        so.x += o.x; so.y += o.y; so.z += o.z; so.w += o.w;
        const size_t dst = ((size_t)(b * V_ + v) * C2_ + c2) * HW_ + p;
        *(uint4*)(xhi + dst) = make_uint4(packhf(e.x, o.x), packhf(e.y, o.y),
                                          packhf(e.z, o.z), packhf(e.w, o.w));
    }
    const float inv = 1.0f / 6.0f;
    const size_t dst = ((size_t)b * C2_ + c2) * HW_ + p;
    *(uint4*)(mhi + dst) = make_uint4(
        packhf(se.x * inv, so.x * inv), packhf(se.y * inv, so.y * inv),
        packhf(se.z * inv, so.z * inv), packhf(se.w * inv, so.w * inv));
}

// ---------------------------------------------------------------------------
// HMMA GEMM, fp16 2-product, fragment-ordered A (LDS.128).
//   4-stage cp.async pipeline, ONE barrier per K-chunk.
//   Y[z][o][p] = sum_c W[o][c] * X[z][c][p];  D = Wh*Xh + Wl*Xh.
// ---------------------------------------------------------------------------
template <int KV, int E16>
__global__ void __launch_bounds__(256) gemm_pk(
    const uint32_t* __restrict__ Wh0, const uint32_t* __restrict__ Wl0,
    const uint32_t* __restrict__ Wh1, const uint32_t* __restrict__ Wl1,
    const uint32_t* __restrict__ Xh,
    void* __restrict__ Y0g, void* __restrict__ Y1g)
{
    extern __shared__ __align__(128) uint32_t smem[];
    const uint32_t sb = smem_u32(smem);

    const uint32_t *Wh, *Wl, *Xhz;
    void* Yv;
    bool f16o;
    if (KV) {
        const int view = blockIdx.z >> 1;
        const int sel = blockIdx.z & 1;
        Wh = sel ? Wh1 : Wh0;
        Wl = sel ? Wl1 : Wl0;
        Xhz = Xh + (size_t)view * C2_ * HW_;
        f16o = (sel == 0);
        Yv = sel ? (void*)((float*)Y1g + (size_t)view * CHW_)
                 : (void*)((__half*)Y0g + (size_t)view * CHW_);
    } else {
        Wh = Wh0; Wl = Wl0;
        Xhz = Xh + (size_t)blockIdx.z * C2_ * HW_;
        f16o = (E16 != 0);
        Yv = E16 ? (void*)((__half*)Y0g + (size_t)blockIdx.z * CHW_)
                 : (void*)((float*)Y0g + (size_t)blockIdx.z * CHW_);
    }

    const int tid = threadIdx.x;
    const int lane = tid & 31;
    const int wid = tid >> 5;
    const int p0 = blockIdx.x * NTT;
    const int ot = blockIdx.y;              // o tile (o0 = ot*128)
    const int o0 = ot * MT;

    // cp.async B indices
    const int b_r  = tid >> 5;          // 0..7 (+8)
    const int b_p4 = (tid & 31) * 4;

    // mma fragment indices
    const int g = lane >> 2;
    const int t = lane & 3;
    const int mwb = (wid & 3) * 32;
    const int nwb = (wid >> 2) * 64;
    const int blk0 = (wid & 3) * 2;     // fragment block for mi=0

    float acc[2][8][4];
#pragma unroll
    for (int mi = 0; mi < 2; ++mi)
#pragma unroll
        for (int ni = 0; ni < 8; ++ni)
#pragma unroll
            for (int j = 0; j < 4; ++j) acc[mi][ni][j] = 0.f;

    auto issue = [&](int kc, int buf) {
        const uint32_t base = sb + buf * BUF_U * 4;
        const uint32_t dAh = base;
        const uint32_t dAl = base + A_U * 4;
        const uint32_t dBh = base + 2 * A_U * 4;
        const size_t wsrc = (size_t)(ot * 8 + kc) * A_U;   // fragment-ordered
#pragma unroll
        for (int r = 0; r < 2; ++r) {
            const uint32_t aoff = r * 1024 + tid * 4;      // u32 units
            cpasync16(dAh + aoff * 4, Wh + wsrc + aoff);
            cpasync16(dAl + aoff * 4, Wl + wsrc + aoff);
            const int row = b_r + r * 8;
            const size_t xsrc = (size_t)(kc * 16 + row) * HW_ + p0 + b_p4;
            cpasync16(dBh + (row * BPAD + b_p4) * 4, Xhz + xsrc);
        }
        CP_COMMIT();
    };

    // prefetch 3 chunks
    issue(0, 0);
    issue(1, 1);
    issue(2, 2);

    for (int kc = 0; kc < NKCH; ++kc) {
        // ensure group kc complete (up to 3 groups in flight)
        if (kc <= NKCH - 3)      CP_WAIT(2);
        else if (kc == NKCH - 2) CP_WAIT(1);
        else                     CP_WAIT(0);
        __syncthreads();
        // safe: all warps past this sync finished reading buf (kc-1)&3 == (kc+3)&3
        if (kc + 3 < NKCH) issue(kc + 3, (kc + 3) & 3);

        const uint32_t* bb = smem + (kc & 3) * BUF_U;
        const uint32_t* sAh = bb;
        const uint32_t* sAl = bb + A_U;
        const uint32_t* sBh = bb + 2 * A_U;

#pragma unroll
        for (int s = 0; s < 2; ++s) {
            const int k2r0 = s * 8 + t;
            const int k2r1 = s * 8 + t + 4;
            uint4 ah[2], al[2];
#pragma unroll
            for (int mi = 0; mi < 2; ++mi) {
                const uint32_t fo = (((blk0 + mi) * 2 + s) * 32 + lane) * 4;
                ah[mi] = *(const uint4*)&sAh[fo];
                al[mi] = *(const uint4*)&sAl[fo];
            }
#pragma unroll
            for (int ni = 0; ni < 8; ++ni) {
                const int n0 = nwb + ni * 8 + g;
                const uint32_t b0 = sBh[k2r0 * BPAD + n0];
                const uint32_t b1 = sBh[k2r1 * BPAD + n0];
                mma16816(acc[0][ni], (const uint32_t*)&ah[0], b0, b1);
                mma16816(acc[1][ni], (const uint32_t*)&ah[1], b0, b1);
                mma16816(acc[0][ni], (const uint32_t*)&al[0], b0, b1);
                mma16816(acc[1][ni], (const uint32_t*)&al[1], b0, b1);
            }
        }
    }

    // epilogue
    if (f16o) {
        __half* Yh = (__half*)Yv;
#pragma unroll
        for (int mi = 0; mi < 2; ++mi) {
            const int o = o0 + mwb + mi * 16 + g;
#pragma unroll
            for (int ni = 0; ni < 8; ++ni) {
                const int p = p0 + nwb + ni * 8 + t * 2;
                *(__half2*)(Yh + (size_t)o * HW_ + p) =
                    __floats2half2_rn(acc[mi][ni][0], acc[mi][ni][1]);
                *(__half2*)(Yh + (size_t)(o + 8) * HW_ + p) =
                    __floats2half2_rn(acc[mi][ni][2], acc[mi][ni][3]);
            }
        }
    } else {
        float* Y = (float*)Yv;
#pragma unroll
        for (int mi = 0; mi < 2; ++mi) {
            const int o = o0 + mwb + mi * 16 + g;
#pragma unroll
            for (int ni = 0; ni < 8; ++ni) {
                const int p = p0 + nwb + ni * 8 + t * 2;
                *(float2*)(Y + (size_t)o * HW_ + p) =
                    make_float2(acc[mi][ni][0], acc[mi][ni][1]);
                *(float2*)(Y + (size_t)(o + 8) * HW_ + p) =
                    make_float2(acc[mi][ni][2], acc[mi][ni][3]);
            }
        }
    }
}

// ---------------------------------------------------------------------------
// Per-pixel cross-view attention. Q,K fp16; V fp32. Emits packed fp16 out.
// ---------------------------------------------------------------------------
__global__ void __launch_bounds__(256) attn_kernel(
    const __half* __restrict__ Q, const __half* __restrict__ K,
    const float* __restrict__ Vv, uint32_t* __restrict__ Ohi)
{
    const int p = ((blockIdx.x & 15) << 8) + threadIdx.x;
    const int bh = blockIdx.x >> 4;
    const int b = bh >> 3;
    const int h = bh & 7;

    const size_t qbase = ((size_t)(b * C_ + h * DH_)) * HW_ + p;

    float q[DH_];
#pragma unroll
    for (int d = 0; d < DH_; ++d) q[d] = __half2float(Q[qbase + (size_t)d * HW_]);

    float s[V_];
#pragma unroll
    for (int v = 0; v < V_; ++v) {
        const size_t kb = ((size_t)((b * V_ + v) * C_ + h * DH_)) * HW_ + p;
        float dot = 0.f;
#pragma unroll
        for (int d = 0; d < DH_; ++d)
            dot += q[d] * __half2float(K[kb + (size_t)d * HW_]);
        s[v] = dot * 0.17677669529663687f;
    }
    float m = s[0];
#pragma unroll
    for (int v = 1; v < V_; ++v) m = fmaxf(m, s[v]);
    float sum = 0.f;
#pragma unroll
    for (int v = 0; v < V_; ++v) { s[v] = expf(s[v] - m); sum += s[v]; }
    const float invsum = 1.f / sum;

    float acc[DH_];
#pragma unroll
    for (int d = 0; d < DH_; ++d) acc[d] = 0.f;
#pragma unroll
    for (int v = 0; v < V_; ++v) {
        const float w = s[v] * invsum;
        const size_t vb = ((size_t)((b * V_ + v) * C_ + h * DH_)) * HW_ + p;
#pragma unroll
        for (int d = 0; d < DH_; ++d) acc[d] += w * Vv[vb + (size_t)d * HW_];
    }
    const size_t obase = ((size_t)(b * C2_ + h * (DH_ / 2))) * HW_ + p;
#pragma unroll
    for (int d2 = 0; d2 < DH_ / 2; ++d2)
        Ohi[obase + (size_t)d2 * HW_] = packhf(acc[d2 * 2], acc[d2 * 2 + 1]);
}

// ---------------------------------------------------------------------------
// kernel_launch
// ---------------------------------------------------------------------------
extern "C" void kernel_launch(void* const* d_in, const int* in_sizes, int n_in,
                              void* d_out, int out_size)
{
    const float* x  = (const float*)d_in[0];
    const float* Wq = (const float*)d_in[1];
    const float* Wk = (const float*)d_in[2];
    const float* Wv = (const float*)d_in[3];
    const float* Wo = (const float*)d_in[4];
    float* out = (float*)d_out;

    void* p;
    cudaGetSymbolAddress(&p, g_xpk_hi);  uint32_t* xhi = (uint32_t*)p;
    cudaGetSymbolAddress(&p, g_xmpk_hi); uint32_t* mhi = (uint32_t*)p;
    cudaGetSymbolAddress(&p, g_wpk_hi);  uint32_t* whi = (uint32_t*)p;
    cudaGetSymbolAddress(&p, g_wpk_lo);  uint32_t* wlo = (uint32_t*)p;
    cudaGetSymbolAddress(&p, g_apk_hi);  uint32_t* ahi = (uint32_t*)p;
    cudaGetSymbolAddress(&p, g_qloc);    __half* qloc = (__half*)p;
    cudaGetSymbolAddress(&p, g_kbuf);    __half* kbuf = (__half*)p;
    cudaGetSymbolAddress(&p, g_vbuf);    float*  vbuf = (float*)p;

    cudaFuncSetAttribute(gemm_pk<0,0>, cudaFuncAttributeMaxDynamicSharedMemorySize, SMEM_MMA);
    cudaFuncSetAttribute(gemm_pk<0,1>, cudaFuncAttributeMaxDynamicSharedMemorySize, SMEM_MMA);
    cudaFuncSetAttribute(gemm_pk<1,1>, cudaFuncAttributeMaxDynamicSharedMemorySize, SMEM_MMA);

    const int WSZ = C_ * C2_;

    prep_w_kernel<<<4 * WSZ / 256, 256>>>(Wq, Wk, Wv, Wo, whi, wlo);
    {
        dim3 g(HW_ / 1024, C2_, B_);
        prep_x_kernel<<<g, 256>>>(x, xhi, mhi);
    }
    {   // Qloc = Wq * xmean  -> fp16
        dim3 g(HW_ / NTT, C_ / MT, B_);
        gemm_pk<0,1><<<g, 256, SMEM_MMA>>>(whi + 0 * WSZ, wlo + 0 * WSZ,
                                           nullptr, nullptr, mhi, qloc, nullptr);
    }
    {   // K (fp16) and V (fp32) projections
        dim3 g(HW_ / NTT, C_ / MT, B_ * V_ * 2);
        gemm_pk<1,1><<<g, 256, SMEM_MMA>>>(whi + 1 * WSZ, wlo + 1 * WSZ,
                                           whi + 2 * WSZ, wlo + 2 * WSZ,
                                           xhi, kbuf, vbuf);
    }
    attn_kernel<<<B_ * NH_ * (HW_ / 256), 256>>>(qloc, kbuf, vbuf, ahi);
    {   // out = Wo * att  -> fp32
        dim3 g(HW_ / NTT, C_ / MT, B_);
        gemm_pk<0,0><<<g, 256, SMEM_MMA>>>(whi + 3 * WSZ, wlo + 3 * WSZ,
                                           nullptr, nullptr, ahi, out, nullptr);
    }
}

// round 11
// speedup vs baseline: 2.0332x; 1.0089x over previous
#include <cuda_runtime.h>
#include <cuda_fp16.h>
#include <cstdint>
#include <math.h>

// ---------------------------------------------------------------------------
// Problem constants
// ---------------------------------------------------------------------------
#define B_   4
#define V_   6
#define C_   256
#define C2_  128
#define HW_  4096
#define NH_  8
#define DH_  32
#define CHW_ (C_ * HW_)

// GEMM tiling
#define MT   128
#define NTT  128
#define KB   32           // k chunk (16 pairs)
#define NKCH (C_ / KB)    // 8

// smem (u32 units):
//   A fragment-ordered: [blk(8)][s(2)][lane(32)][4] = 2048 u32 per matrix
//   B pair-packed:      [sl(8)][p(128)] uint2, pitch 132 uint2 -> 2112 u32
#define A_U    2048
#define BP2    132                        // B pitch in uint2
#define B_U    (8 * BP2 * 2)              // 2112 u32
#define BUF_U  (2 * A_U + B_U)            // 6208
#define NSTG   4
#define SMEM_MMA (NSTG * BUF_U * 4)       // 99328 B (2 CTAs/SM)

// X pair layout: per z, [kc(8)][sl(8)][p(4096)] uint2  -> 64*HW_ uint2 per z
#define XZ_U2  (64 * HW_)

// ---------------------------------------------------------------------------
// Scratch (device globals)
// ---------------------------------------------------------------------------
__device__ __align__(128) uint2   g_xpk [B_ * V_ * XZ_U2];   // pair-packed X
__device__ __align__(128) uint2   g_xmpk[B_ * XZ_U2];        // pair-packed xmean
__device__ __align__(128) uint32_t g_wpk_hi[4 * C_ * C2_];   // fragment order
__device__ __align__(128) uint32_t g_wpk_lo[4 * C_ * C2_];
__device__ __align__(128) uint2   g_apk [B_ * XZ_U2];        // pair-packed attn out
__device__ __align__(128) __half  g_qloc[B_ * CHW_];
__device__ __align__(128) __half  g_kbuf[B_ * V_ * CHW_];
__device__ __align__(128) float   g_vbuf[B_ * V_ * CHW_];

// ---------------------------------------------------------------------------
// Helpers
// ---------------------------------------------------------------------------
__device__ __forceinline__ uint32_t smem_u32(const void* p) {
    uint32_t a;
    asm("{ .reg .u64 t; cvta.to.shared.u64 t, %1; cvt.u32.u64 %0, t; }" : "=r"(a) : "l"(p));
    return a;
}
__device__ __forceinline__ uint32_t packhf(float e0, float e1) {
    return ((uint32_t)__half_as_ushort(__float2half_rn(e1)) << 16)
         | (uint32_t)__half_as_ushort(__float2half_rn(e0));
}
__device__ __forceinline__ float hfres(float v) {
    return v - __half2float(__float2half_rn(v));
}
__device__ __forceinline__ void mma16816(float* c, const uint32_t* a,
                                         uint32_t b0, uint32_t b1) {
    asm volatile(
        "mma.sync.aligned.m16n8k16.row.col.f32.f16.f16.f32 "
        "{%0,%1,%2,%3}, {%4,%5,%6,%7}, {%8,%9}, {%0,%1,%2,%3};\n"
        : "+f"(c[0]), "+f"(c[1]), "+f"(c[2]), "+f"(c[3])
        : "r"(a[0]), "r"(a[1]), "r"(a[2]), "r"(a[3]), "r"(b0), "r"(b1));
}
__device__ __forceinline__ void cpasync16(uint32_t dst, const void* src) {
    asm volatile("cp.async.cg.shared.global [%0], [%1], 16;\n" :: "r"(dst), "l"(src));
}
#define CP_COMMIT() asm volatile("cp.async.commit_group;\n" ::: "memory")
#define CP_WAIT(n)  asm volatile("cp.async.wait_group %0;\n" :: "n"(n) : "memory")

// ---------------------------------------------------------------------------
// prep_w: split + pair-pack weights into MMA FRAGMENT ORDER (unchanged).
// ---------------------------------------------------------------------------
__global__ void __launch_bounds__(256) prep_w_kernel(
    const float* __restrict__ Wq, const float* __restrict__ Wk,
    const float* __restrict__ Wv, const float* __restrict__ Wo,
    uint32_t* __restrict__ hi, uint32_t* __restrict__ lo)
{
    const int i = blockIdx.x * 256 + threadIdx.x;
    const int w = i >> 15;
    const int r = i & 32767;
    const int j    = r & 3;
    const int lane = (r >> 2) & 31;
    const int s    = (r >> 7) & 1;
    const int blk  = (r >> 8) & 7;
    const int kc   = (r >> 11) & 7;
    const int ot   = (r >> 14) & 1;
    const int o  = ot * 128 + blk * 16 + (j & 1) * 8 + (lane >> 2);
    const int k2 = kc * 16 + s * 8 + (j >> 1) * 4 + (lane & 3);
    const float* src = (w == 0) ? Wq : (w == 1) ? Wk : (w == 2) ? Wv : Wo;
    const float2 f = *(const float2*)(src + o * C_ + k2 * 2);
    hi[i] = packhf(f.x, f.y);
    lo[i] = packhf(hfres(f.x), hfres(f.y));
}

// ---------------------------------------------------------------------------
// prep_x: fused view-mean + fp16 pack into PAIR layout.
//   Output uint2 at [z][kc][sl=s*4+t][p]:
//     .x = packhf(x[c=2*c2a], x[2*c2a+1]),  c2a = kc*16 + s*8 + t
//     .y = packhf(x[c=2*c2b], x[2*c2b+1]),  c2b = c2a + 4
// grid (HW/1024, 64, B), block 256; thread handles 4 p's.
// ---------------------------------------------------------------------------
__global__ void __launch_bounds__(256) prep_x_kernel(
    const float* __restrict__ x,
    uint2* __restrict__ xp, uint2* __restrict__ mp)
{
    const int p  = blockIdx.x * 1024 + threadIdx.x * 4;
    const int sl = blockIdx.y & 7;
    const int kc = blockIdx.y >> 3;
    const int b  = blockIdx.z;
    const int s = sl >> 2, t = sl & 3;
    const int ca = (kc * 16 + s * 8 + t) * 2;    // fp32 channel row (even) of pair a

    float4 sea = make_float4(0,0,0,0), soa = sea, seb = sea, sob = sea;
#pragma unroll
    for (int v = 0; v < V_; ++v) {
        const float* base = x + ((size_t)((b * V_ + v) * C_) + ca) * HW_ + p;
        const float4 ea = *(const float4*)base;
        const float4 oa = *(const float4*)(base + HW_);
        const float4 eb = *(const float4*)(base + 8 * HW_);
        const float4 ob = *(const float4*)(base + 9 * HW_);
        sea.x += ea.x; sea.y += ea.y; sea.z += ea.z; sea.w += ea.w;
        soa.x += oa.x; soa.y += oa.y; soa.z += oa.z; soa.w += oa.w;
        seb.x += eb.x; seb.y += eb.y; seb.z += eb.z; seb.w += eb.w;
        sob.x += ob.x; sob.y += ob.y; sob.z += ob.z; sob.w += ob.w;
        uint2* dst = xp + ((size_t)(b * V_ + v) * 64 + blockIdx.y) * HW_ + p;
        dst[0] = make_uint2(packhf(ea.x, oa.x), packhf(eb.x, ob.x));
        dst[1] = make_uint2(packhf(ea.y, oa.y), packhf(eb.y, ob.y));
        dst[2] = make_uint2(packhf(ea.z, oa.z), packhf(eb.z, ob.z));
        dst[3] = make_uint2(packhf(ea.w, oa.w), packhf(eb.w, ob.w));
    }
    const float inv = 1.0f / 6.0f;
    uint2* dst = mp + ((size_t)b * 64 + blockIdx.y) * HW_ + p;
    dst[0] = make_uint2(packhf(sea.x * inv, soa.x * inv), packhf(seb.x * inv, sob.x * inv));
    dst[1] = make_uint2(packhf(sea.y * inv, soa.y * inv), packhf(seb.y * inv, sob.y * inv));
    dst[2] = make_uint2(packhf(sea.z * inv, soa.z * inv), packhf(seb.z * inv, sob.z * inv));
    dst[3] = make_uint2(packhf(sea.w * inv, soa.w * inv), packhf(seb.w * inv, sob.w * inv));
}

// ---------------------------------------------------------------------------
// HMMA GEMM, fp16 2-product. A: fragment-ordered LDS.128. B: pair LDS.64.
//   4-stage cp.async pipeline, one barrier per K-chunk.
// ---------------------------------------------------------------------------
template <int KV, int E16>
__global__ void __launch_bounds__(256) gemm_pk(
    const uint32_t* __restrict__ Wh0, const uint32_t* __restrict__ Wl0,
    const uint32_t* __restrict__ Wh1, const uint32_t* __restrict__ Wl1,
    const uint2* __restrict__ Xh,
    void* __restrict__ Y0g, void* __restrict__ Y1g)
{
    extern __shared__ __align__(128) uint32_t smem[];
    const uint32_t sb = smem_u32(smem);

    const uint32_t *Wh, *Wl;
    const uint2* Xhz;
    void* Yv;
    bool f16o;
    if (KV) {
        const int view = blockIdx.z >> 1;
        const int sel = blockIdx.z & 1;
        Wh = sel ? Wh1 : Wh0;
        Wl = sel ? Wl1 : Wl0;
        Xhz = Xh + (size_t)view * XZ_U2;
        f16o = (sel == 0);
        Yv = sel ? (void*)((float*)Y1g + (size_t)view * CHW_)
                 : (void*)((__half*)Y0g + (size_t)view * CHW_);
    } else {
        Wh = Wh0; Wl = Wl0;
        Xhz = Xh + (size_t)blockIdx.z * XZ_U2;
        f16o = (E16 != 0);
        Yv = E16 ? (void*)((__half*)Y0g + (size_t)blockIdx.z * CHW_)
                 : (void*)((float*)Y0g + (size_t)blockIdx.z * CHW_);
    }

    const int tid = threadIdx.x;
    const int lane = tid & 31;
    const int wid = tid >> 5;
    const int p0 = blockIdx.x * NTT;
    const int ot = blockIdx.y;
    const int o0 = ot * MT;

    // cp.async B indices: row = sl (0..7), 2 iterations cover 128 p
    const int b_row = tid >> 5;
    const int b_pc  = (tid & 31) * 2;    // p offset (2 p per 16B)

    // mma fragment indices
    const int g = lane >> 2;
    const int t = lane & 3;
    const int mwb = (wid & 3) * 32;
    const int nwb = (wid >> 2) * 64;
    const int blk0 = (wid & 3) * 2;

    float acc[2][8][4];
#pragma unroll
    for (int mi = 0; mi < 2; ++mi)
#pragma unroll
        for (int ni = 0; ni < 8; ++ni)
#pragma unroll
            for (int j = 0; j < 4; ++j) acc[mi][ni][j] = 0.f;

    auto issue = [&](int kc, int buf) {
        const uint32_t base = sb + buf * BUF_U * 4;
        const uint32_t dAh = base;
        const uint32_t dAl = base + A_U * 4;
        const uint32_t dBh = base + 2 * A_U * 4;
        const size_t wsrc = (size_t)(ot * 8 + kc) * A_U;
#pragma unroll
        for (int r = 0; r < 2; ++r) {
            const uint32_t aoff = r * 1024 + tid * 4;
            cpasync16(dAh + aoff * 4, Wh + wsrc + aoff);
            cpasync16(dAl + aoff * 4, Wl + wsrc + aoff);
            const int pc = b_pc + r * 64;
            cpasync16(dBh + b_row * (BP2 * 8) + pc * 8,
                      Xhz + (size_t)(kc * 8 + b_row) * HW_ + p0 + pc);
        }
        CP_COMMIT();
    };

    issue(0, 0);
    issue(1, 1);
    issue(2, 2);

    for (int kc = 0; kc < NKCH; ++kc) {
        if (kc <= NKCH - 3)      CP_WAIT(2);
        else if (kc == NKCH - 2) CP_WAIT(1);
        else                     CP_WAIT(0);
        __syncthreads();
        if (kc + 3 < NKCH) issue(kc + 3, (kc + 3) & 3);

        const uint32_t* bb = smem + (kc & 3) * BUF_U;
        const uint32_t* sAh = bb;
        const uint32_t* sAl = bb + A_U;
        const uint2* sB2 = (const uint2*)(bb + 2 * A_U);

#pragma unroll
        for (int s = 0; s < 2; ++s) {
            uint4 ah[2], al[2];
#pragma unroll
            for (int mi = 0; mi < 2; ++mi) {
                const uint32_t fo = (((blk0 + mi) * 2 + s) * 32 + lane) * 4;
                ah[mi] = *(const uint4*)&sAh[fo];
                al[mi] = *(const uint4*)&sAl[fo];
            }
            const int brow = (s * 4 + t) * BP2;
#pragma unroll
            for (int ni = 0; ni < 8; ++ni) {
                const int n0 = nwb + ni * 8 + g;
                const uint2 bv = sB2[brow + n0];
                mma16816(acc[0][ni], (const uint32_t*)&ah[0], bv.x, bv.y);
                mma16816(acc[1][ni], (const uint32_t*)&ah[1], bv.x, bv.y);
                mma16816(acc[0][ni], (const uint32_t*)&al[0], bv.x, bv.y);
                mma16816(acc[1][ni], (const uint32_t*)&al[1], bv.x, bv.y);
            }
        }
    }

    // epilogue
    if (f16o) {
        __half* Yh = (__half*)Yv;
#pragma unroll
        for (int mi = 0; mi < 2; ++mi) {
            const int o = o0 + mwb + mi * 16 + g;
#pragma unroll
            for (int ni = 0; ni < 8; ++ni) {
                const int p = p0 + nwb + ni * 8 + t * 2;
                *(__half2*)(Yh + (size_t)o * HW_ + p) =
                    __floats2half2_rn(acc[mi][ni][0], acc[mi][ni][1]);
                *(__half2*)(Yh + (size_t)(o + 8) * HW_ + p) =
                    __floats2half2_rn(acc[mi][ni][2], acc[mi][ni][3]);
            }
        }
    } else {
        float* Y = (float*)Yv;
#pragma unroll
        for (int mi = 0; mi < 2; ++mi) {
            const int o = o0 + mwb + mi * 16 + g;
#pragma unroll
            for (int ni = 0; ni < 8; ++ni) {
                const int p = p0 + nwb + ni * 8 + t * 2;
                *(float2*)(Y + (size_t)o * HW_ + p) =
                    make_float2(acc[mi][ni][0], acc[mi][ni][1]);
                *(float2*)(Y + (size_t)(o + 8) * HW_ + p) =
                    make_float2(acc[mi][ni][2], acc[mi][ni][3]);
            }
        }
    }
}

// ---------------------------------------------------------------------------
// Per-pixel cross-view attention. Q,K fp16; V fp32. Emits PAIR-layout fp16.
//   Output uint2 at [b][kc=h][sl=s*4+t][p]:
//     d = s*8+t:  .x = packhf(acc[2d], acc[2d+1]), .y = packhf(acc[2(d+4)], acc[2(d+4)+1])
// ---------------------------------------------------------------------------
__global__ void __launch_bounds__(256) attn_kernel(
    const __half* __restrict__ Q, const __half* __restrict__ K,
    const float* __restrict__ Vv, uint2* __restrict__ Op)
{
    const int p = ((blockIdx.x & 15) << 8) + threadIdx.x;
    const int bh = blockIdx.x >> 4;
    const int b = bh >> 3;
    const int h = bh & 7;

    const size_t qbase = ((size_t)(b * C_ + h * DH_)) * HW_ + p;

    float q[DH_];
#pragma unroll
    for (int d = 0; d < DH_; ++d) q[d] = __half2float(Q[qbase + (size_t)d * HW_]);

    float s[V_];
#pragma unroll
    for (int v = 0; v < V_; ++v) {
        const size_t kb = ((size_t)((b * V_ + v) * C_ + h * DH_)) * HW_ + p;
        float dot = 0.f;
#pragma unroll
        for (int d = 0; d < DH_; ++d)
            dot += q[d] * __half2float(K[kb + (size_t)d * HW_]);
        s[v] = dot * 0.17677669529663687f;
    }
    float m = s[0];
#pragma unroll
    for (int v = 1; v < V_; ++v) m = fmaxf(m, s[v]);
    float sum = 0.f;
#pragma unroll
    for (int v = 0; v < V_; ++v) { s[v] = expf(s[v] - m); sum += s[v]; }
    const float invsum = 1.f / sum;

    float acc[DH_];
#pragma unroll
    for (int d = 0; d < DH_; ++d) acc[d] = 0.f;
#pragma unroll
    for (int v = 0; v < V_; ++v) {
        const float w = s[v] * invsum;
        const size_t vb = ((size_t)((b * V_ + v) * C_ + h * DH_)) * HW_ + p;
#pragma unroll
        for (int d = 0; d < DH_; ++d) acc[d] += w * Vv[vb + (size_t)d * HW_];
    }
#pragma unroll
    for (int sl = 0; sl < 8; ++sl) {
        const int d = (sl >> 2) * 8 + (sl & 3);    // s*8 + t
        Op[((size_t)(b * 8 + h) * 8 + sl) * HW_ + p] =
            make_uint2(packhf(acc[2 * d], acc[2 * d + 1]),
                       packhf(acc[2 * (d + 4)], acc[2 * (d + 4) + 1]));
    }
}

// ---------------------------------------------------------------------------
// kernel_launch
// ---------------------------------------------------------------------------
extern "C" void kernel_launch(void* const* d_in, const int* in_sizes, int n_in,
                              void* d_out, int out_size)
{
    const float* x  = (const float*)d_in[0];
    const float* Wq = (const float*)d_in[1];
    const float* Wk = (const float*)d_in[2];
    const float* Wv = (const float*)d_in[3];
    const float* Wo = (const float*)d_in[4];
    float* out = (float*)d_out;

    void* p;
    cudaGetSymbolAddress(&p, g_xpk);    uint2* xp = (uint2*)p;
    cudaGetSymbolAddress(&p, g_xmpk);   uint2* mp = (uint2*)p;
    cudaGetSymbolAddress(&p, g_wpk_hi); uint32_t* whi = (uint32_t*)p;
    cudaGetSymbolAddress(&p, g_wpk_lo); uint32_t* wlo = (uint32_t*)p;
    cudaGetSymbolAddress(&p, g_apk);    uint2* ap = (uint2*)p;
    cudaGetSymbolAddress(&p, g_qloc);   __half* qloc = (__half*)p;
    cudaGetSymbolAddress(&p, g_kbuf);   __half* kbuf = (__half*)p;
    cudaGetSymbolAddress(&p, g_vbuf);   float*  vbuf = (float*)p;

    cudaFuncSetAttribute(gemm_pk<0,0>, cudaFuncAttributeMaxDynamicSharedMemorySize, SMEM_MMA);
    cudaFuncSetAttribute(gemm_pk<0,1>, cudaFuncAttributeMaxDynamicSharedMemorySize, SMEM_MMA);
    cudaFuncSetAttribute(gemm_pk<1,1>, cudaFuncAttributeMaxDynamicSharedMemorySize, SMEM_MMA);

    const int WSZ = C_ * C2_;

    prep_w_kernel<<<4 * WSZ / 256, 256>>>(Wq, Wk, Wv, Wo, whi, wlo);
    {
        dim3 g(HW_ / 1024, 64, B_);
        prep_x_kernel<<<g, 256>>>(x, xp, mp);
    }
    {   // Qloc = Wq * xmean  -> fp16
        dim3 g(HW_ / NTT, C_ / MT, B_);
        gemm_pk<0,1><<<g, 256, SMEM_MMA>>>(whi + 0 * WSZ, wlo + 0 * WSZ,
                                           nullptr, nullptr, mp, qloc, nullptr);
    }
    {   // K (fp16) and V (fp32) projections
        dim3 g(HW_ / NTT, C_ / MT, B_ * V_ * 2);
        gemm_pk<1,1><<<g, 256, SMEM_MMA>>>(whi + 1 * WSZ, wlo + 1 * WSZ,
                                           whi + 2 * WSZ, wlo + 2 * WSZ,
                                           xp, kbuf, vbuf);
    }
    attn_kernel<<<B_ * NH_ * (HW_ / 256), 256>>>(qloc, kbuf, vbuf, ap);
    {   // out = Wo * att  -> fp32
        dim3 g(HW_ / NTT, C_ / MT, B_);
        gemm_pk<0,0><<<g, 256, SMEM_MMA>>>(whi + 3 * WSZ, wlo + 3 * WSZ,
                                           nullptr, nullptr, ap, out, nullptr);
    }
}

// round 12
// speedup vs baseline: 2.4855x; 1.2224x over previous
#include <cuda_runtime.h>
#include <cuda_fp16.h>
#include <cstdint>
#include <math.h>

// ---------------------------------------------------------------------------
// Problem constants
// ---------------------------------------------------------------------------
#define B_   4
#define V_   6
#define C_   256
#define C2_  128
#define HW_  4096
#define NH_  8
#define DH_  32
#define CHW_ (C_ * HW_)

// GEMM tiling
#define MT   128
#define NTT  128
#define KB   32           // k chunk (16 pairs)
#define NKCH (C_ / KB)    // 8

// smem (u32 units):
//   A fragment-ordered: [blk(8)][s(2)][lane(32)][4] = 2048 u32 per matrix
//   B pair-packed:      [sl(8)][p(128)] uint2, pitch 132 uint2 -> 2112 u32
#define A_U    2048
#define BP2    132
#define B_U    (8 * BP2 * 2)              // 2112 u32
#define NSTG   4
// buffer stride depends on #products: NP*A_U + B_U
#define BUFU1  (A_U + B_U)                // 4160
#define BUFU2  (2 * A_U + B_U)            // 6208
#define SMEM1  (NSTG * BUFU1 * 4)         // 66560 B
#define SMEM2  (NSTG * BUFU2 * 4)         // 99328 B

// X pair layout: per z, [kc(8)][sl(8)][p(4096)] uint2
#define XZ_U2  (64 * HW_)

// ---------------------------------------------------------------------------
// Scratch (device globals)
// ---------------------------------------------------------------------------
__device__ __align__(128) uint2   g_xpk [B_ * V_ * XZ_U2];   // pair-packed X
__device__ __align__(128) uint2   g_xmpk[B_ * XZ_U2];        // pair-packed xmean
__device__ __align__(128) uint32_t g_wpk_hi[4 * C_ * C2_];   // fragment order
__device__ __align__(128) uint32_t g_wpk_lo[4 * C_ * C2_];
__device__ __align__(128) uint2   g_apk [B_ * XZ_U2];        // pair-packed attn out
__device__ __align__(128) __half  g_qloc[B_ * CHW_];
__device__ __align__(128) __half  g_kbuf[B_ * V_ * CHW_];
__device__ __align__(128) float   g_vbuf[B_ * V_ * CHW_];

// ---------------------------------------------------------------------------
// Helpers
// ---------------------------------------------------------------------------
__device__ __forceinline__ uint32_t smem_u32(const void* p) {
    uint32_t a;
    asm("{ .reg .u64 t; cvta.to.shared.u64 t, %1; cvt.u32.u64 %0, t; }" : "=r"(a) : "l"(p));
    return a;
}
__device__ __forceinline__ uint32_t packhf(float e0, float e1) {
    return ((uint32_t)__half_as_ushort(__float2half_rn(e1)) << 16)
         | (uint32_t)__half_as_ushort(__float2half_rn(e0));
}
__device__ __forceinline__ float hfres(float v) {
    return v - __half2float(__float2half_rn(v));
}
__device__ __forceinline__ void mma16816(float* c, const uint32_t* a,
                                         uint32_t b0, uint32_t b1) {
    asm volatile(
        "mma.sync.aligned.m16n8k16.row.col.f32.f16.f16.f32 "
        "{%0,%1,%2,%3}, {%4,%5,%6,%7}, {%8,%9}, {%0,%1,%2,%3};\n"
        : "+f"(c[0]), "+f"(c[1]), "+f"(c[2]), "+f"(c[3])
        : "r"(a[0]), "r"(a[1]), "r"(a[2]), "r"(a[3]), "r"(b0), "r"(b1));
}
__device__ __forceinline__ void cpasync16(uint32_t dst, const void* src) {
    asm volatile("cp.async.cg.shared.global [%0], [%1], 16;\n" :: "r"(dst), "l"(src));
}
#define CP_COMMIT() asm volatile("cp.async.commit_group;\n" ::: "memory")
#define CP_WAIT(n)  asm volatile("cp.async.wait_group %0;\n" :: "n"(n) : "memory")

// ---------------------------------------------------------------------------
// prep_w: split + pair-pack weights into MMA FRAGMENT ORDER (unchanged).
// ---------------------------------------------------------------------------
__global__ void __launch_bounds__(256) prep_w_kernel(
    const float* __restrict__ Wq, const float* __restrict__ Wk,
    const float* __restrict__ Wv, const float* __restrict__ Wo,
    uint32_t* __restrict__ hi, uint32_t* __restrict__ lo)
{
    const int i = blockIdx.x * 256 + threadIdx.x;
    const int w = i >> 15;
    const int r = i & 32767;
    const int j    = r & 3;
    const int lane = (r >> 2) & 31;
    const int s    = (r >> 7) & 1;
    const int blk  = (r >> 8) & 7;
    const int kc   = (r >> 11) & 7;
    const int ot   = (r >> 14) & 1;
    const int o  = ot * 128 + blk * 16 + (j & 1) * 8 + (lane >> 2);
    const int k2 = kc * 16 + s * 8 + (j >> 1) * 4 + (lane & 3);
    const float* src = (w == 0) ? Wq : (w == 1) ? Wk : (w == 2) ? Wv : Wo;
    const float2 f = *(const float2*)(src + o * C_ + k2 * 2);
    hi[i] = packhf(f.x, f.y);
    lo[i] = packhf(hfres(f.x), hfres(f.y));
}

// ---------------------------------------------------------------------------
// prep_x: fused view-mean + fp16 pack into PAIR layout (unchanged).
// ---------------------------------------------------------------------------
__global__ void __launch_bounds__(256) prep_x_kernel(
    const float* __restrict__ x,
    uint2* __restrict__ xp, uint2* __restrict__ mp)
{
    const int p  = blockIdx.x * 1024 + threadIdx.x * 4;
    const int sl = blockIdx.y & 7;
    const int kc = blockIdx.y >> 3;
    const int b  = blockIdx.z;
    const int s = sl >> 2, t = sl & 3;
    const int ca = (kc * 16 + s * 8 + t) * 2;

    float4 sea = make_float4(0,0,0,0), soa = sea, seb = sea, sob = sea;
#pragma unroll
    for (int v = 0; v < V_; ++v) {
        const float* base = x + ((size_t)((b * V_ + v) * C_) + ca) * HW_ + p;
        const float4 ea = *(const float4*)base;
        const float4 oa = *(const float4*)(base + HW_);
        const float4 eb = *(const float4*)(base + 8 * HW_);
        const float4 ob = *(const float4*)(base + 9 * HW_);
        sea.x += ea.x; sea.y += ea.y; sea.z += ea.z; sea.w += ea.w;
        soa.x += oa.x; soa.y += oa.y; soa.z += oa.z; soa.w += oa.w;
        seb.x += eb.x; seb.y += eb.y; seb.z += eb.z; seb.w += eb.w;
        sob.x += ob.x; sob.y += ob.y; sob.z += ob.z; sob.w += ob.w;
        uint2* dst = xp + ((size_t)(b * V_ + v) * 64 + blockIdx.y) * HW_ + p;
        dst[0] = make_uint2(packhf(ea.x, oa.x), packhf(eb.x, ob.x));
        dst[1] = make_uint2(packhf(ea.y, oa.y), packhf(eb.y, ob.y));
        dst[2] = make_uint2(packhf(ea.z, oa.z), packhf(eb.z, ob.z));
        dst[3] = make_uint2(packhf(ea.w, oa.w), packhf(eb.w, ob.w));
    }
    const float inv = 1.0f / 6.0f;
    uint2* dst = mp + ((size_t)b * 64 + blockIdx.y) * HW_ + p;
    dst[0] = make_uint2(packhf(sea.x * inv, soa.x * inv), packhf(seb.x * inv, sob.x * inv));
    dst[1] = make_uint2(packhf(sea.y * inv, soa.y * inv), packhf(seb.y * inv, sob.y * inv));
    dst[2] = make_uint2(packhf(sea.z * inv, soa.z * inv), packhf(seb.z * inv, sob.z * inv));
    dst[3] = make_uint2(packhf(sea.w * inv, soa.w * inv), packhf(seb.w * inv, sob.w * inv));
}

// ---------------------------------------------------------------------------
// HMMA GEMM. NP = number of W products (1: D=Wh*Xh, 2: +Wl*Xh).
//   A: fragment-ordered LDS.128. B: pair LDS.64. 4-stage, 1 barrier/chunk.
// ---------------------------------------------------------------------------
template <int KV, int E16, int NP>
__global__ void __launch_bounds__(256) gemm_pk(
    const uint32_t* __restrict__ Wh0, const uint32_t* __restrict__ Wl0,
    const uint32_t* __restrict__ Wh1, const uint32_t* __restrict__ Wl1,
    const uint2* __restrict__ Xh,
    void* __restrict__ Y0g, void* __restrict__ Y1g)
{
    constexpr int BUFU = NP * A_U + B_U;
    extern __shared__ __align__(128) uint32_t smem[];
    const uint32_t sb = smem_u32(smem);

    const uint32_t *Wh, *Wl;
    const uint2* Xhz;
    void* Yv;
    bool f16o;
    if (KV) {
        const int view = blockIdx.z >> 1;
        const int sel = blockIdx.z & 1;
        Wh = sel ? Wh1 : Wh0;
        Wl = sel ? Wl1 : Wl0;
        Xhz = Xh + (size_t)view * XZ_U2;
        f16o = (sel == 0);
        Yv = sel ? (void*)((float*)Y1g + (size_t)view * CHW_)
                 : (void*)((__half*)Y0g + (size_t)view * CHW_);
    } else {
        Wh = Wh0; Wl = Wl0;
        Xhz = Xh + (size_t)blockIdx.z * XZ_U2;
        f16o = (E16 != 0);
        Yv = E16 ? (void*)((__half*)Y0g + (size_t)blockIdx.z * CHW_)
                 : (void*)((float*)Y0g + (size_t)blockIdx.z * CHW_);
    }

    const int tid = threadIdx.x;
    const int lane = tid & 31;
    const int wid = tid >> 5;
    const int p0 = blockIdx.x * NTT;
    const int ot = blockIdx.y;
    const int o0 = ot * MT;

    const int b_row = tid >> 5;
    const int b_pc  = (tid & 31) * 2;

    const int g = lane >> 2;
    const int t = lane & 3;
    const int mwb = (wid & 3) * 32;
    const int nwb = (wid >> 2) * 64;
    const int blk0 = (wid & 3) * 2;

    float acc[2][8][4];
#pragma unroll
    for (int mi = 0; mi < 2; ++mi)
#pragma unroll
        for (int ni = 0; ni < 8; ++ni)
#pragma unroll
            for (int j = 0; j < 4; ++j) acc[mi][ni][j] = 0.f;

    auto issue = [&](int kc, int buf) {
        const uint32_t base = sb + buf * BUFU * 4;
        const uint32_t dAh = base;
        const uint32_t dAl = base + A_U * 4;                 // used only if NP==2
        const uint32_t dBh = base + NP * A_U * 4;
        const size_t wsrc = (size_t)(ot * 8 + kc) * A_U;
#pragma unroll
        for (int r = 0; r < 2; ++r) {
            const uint32_t aoff = r * 1024 + tid * 4;
            cpasync16(dAh + aoff * 4, Wh + wsrc + aoff);
            if (NP == 2) cpasync16(dAl + aoff * 4, Wl + wsrc + aoff);
            const int pc = b_pc + r * 64;
            cpasync16(dBh + b_row * (BP2 * 8) + pc * 8,
                      Xhz + (size_t)(kc * 8 + b_row) * HW_ + p0 + pc);
        }
        CP_COMMIT();
    };

    issue(0, 0);
    issue(1, 1);
    issue(2, 2);

    for (int kc = 0; kc < NKCH; ++kc) {
        if (kc <= NKCH - 3)      CP_WAIT(2);
        else if (kc == NKCH - 2) CP_WAIT(1);
        else                     CP_WAIT(0);
        __syncthreads();
        if (kc + 3 < NKCH) issue(kc + 3, (kc + 3) & 3);

        const uint32_t* bb = smem + (kc & 3) * BUFU;
        const uint32_t* sAh = bb;
        const uint32_t* sAl = bb + A_U;
        const uint2* sB2 = (const uint2*)(bb + NP * A_U);

#pragma unroll
        for (int s = 0; s < 2; ++s) {
            uint4 ah[2], al[2];
#pragma unroll
            for (int mi = 0; mi < 2; ++mi) {
                const uint32_t fo = (((blk0 + mi) * 2 + s) * 32 + lane) * 4;
                ah[mi] = *(const uint4*)&sAh[fo];
                if (NP == 2) al[mi] = *(const uint4*)&sAl[fo];
            }
            const int brow = (s * 4 + t) * BP2;
#pragma unroll
            for (int ni = 0; ni < 8; ++ni) {
                const int n0 = nwb + ni * 8 + g;
                const uint2 bv = sB2[brow + n0];
                mma16816(acc[0][ni], (const uint32_t*)&ah[0], bv.x, bv.y);
                mma16816(acc[1][ni], (const uint32_t*)&ah[1], bv.x, bv.y);
                if (NP == 2) {
                    mma16816(acc[0][ni], (const uint32_t*)&al[0], bv.x, bv.y);
                    mma16816(acc[1][ni], (const uint32_t*)&al[1], bv.x, bv.y);
                }
            }
        }
    }

    // epilogue
    if (f16o) {
        __half* Yh = (__half*)Yv;
#pragma unroll
        for (int mi = 0; mi < 2; ++mi) {
            const int o = o0 + mwb + mi * 16 + g;
#pragma unroll
            for (int ni = 0; ni < 8; ++ni) {
                const int p = p0 + nwb + ni * 8 + t * 2;
                *(__half2*)(Yh + (size_t)o * HW_ + p) =
                    __floats2half2_rn(acc[mi][ni][0], acc[mi][ni][1]);
                *(__half2*)(Yh + (size_t)(o + 8) * HW_ + p) =
                    __floats2half2_rn(acc[mi][ni][2], acc[mi][ni][3]);
            }
        }
    } else {
        float* Y = (float*)Yv;
#pragma unroll
        for (int mi = 0; mi < 2; ++mi) {
            const int o = o0 + mwb + mi * 16 + g;
#pragma unroll
            for (int ni = 0; ni < 8; ++ni) {
                const int p = p0 + nwb + ni * 8 + t * 2;
                *(float2*)(Y + (size_t)o * HW_ + p) =
                    make_float2(acc[mi][ni][0], acc[mi][ni][1]);
                *(float2*)(Y + (size_t)(o + 8) * HW_ + p) =
                    make_float2(acc[mi][ni][2], acc[mi][ni][3]);
            }
        }
    }
}

// ---------------------------------------------------------------------------
// Per-pixel cross-view attention (unchanged). Emits PAIR-layout fp16.
// ---------------------------------------------------------------------------
__global__ void __launch_bounds__(256) attn_kernel(
    const __half* __restrict__ Q, const __half* __restrict__ K,
    const float* __restrict__ Vv, uint2* __restrict__ Op)
{
    const int p = ((blockIdx.x & 15) << 8) + threadIdx.x;
    const int bh = blockIdx.x >> 4;
    const int b = bh >> 3;
    const int h = bh & 7;

    const size_t qbase = ((size_t)(b * C_ + h * DH_)) * HW_ + p;

    float q[DH_];
#pragma unroll
    for (int d = 0; d < DH_; ++d) q[d] = __half2float(Q[qbase + (size_t)d * HW_]);

    float s[V_];
#pragma unroll
    for (int v = 0; v < V_; ++v) {
        const size_t kb = ((size_t)((b * V_ + v) * C_ + h * DH_)) * HW_ + p;
        float dot = 0.f;
#pragma unroll
        for (int d = 0; d < DH_; ++d)
            dot += q[d] * __half2float(K[kb + (size_t)d * HW_]);
        s[v] = dot * 0.17677669529663687f;
    }
    float m = s[0];
#pragma unroll
    for (int v = 1; v < V_; ++v) m = fmaxf(m, s[v]);
    float sum = 0.f;
#pragma unroll
    for (int v = 0; v < V_; ++v) { s[v] = expf(s[v] - m); sum += s[v]; }
    const float invsum = 1.f / sum;

    float acc[DH_];
#pragma unroll
    for (int d = 0; d < DH_; ++d) acc[d] = 0.f;
#pragma unroll
    for (int v = 0; v < V_; ++v) {
        const float w = s[v] * invsum;
        const size_t vb = ((size_t)((b * V_ + v) * C_ + h * DH_)) * HW_ + p;
#pragma unroll
        for (int d = 0; d < DH_; ++d) acc[d] += w * Vv[vb + (size_t)d * HW_];
    }
#pragma unroll
    for (int sl = 0; sl < 8; ++sl) {
        const int d = (sl >> 2) * 8 + (sl & 3);
        Op[((size_t)(b * 8 + h) * 8 + sl) * HW_ + p] =
            make_uint2(packhf(acc[2 * d], acc[2 * d + 1]),
                       packhf(acc[2 * (d + 4)], acc[2 * (d + 4) + 1]));
    }
}

// ---------------------------------------------------------------------------
// kernel_launch
// ---------------------------------------------------------------------------
extern "C" void kernel_launch(void* const* d_in, const int* in_sizes, int n_in,
                              void* d_out, int out_size)
{
    const float* x  = (const float*)d_in[0];
    const float* Wq = (const float*)d_in[1];
    const float* Wk = (const float*)d_in[2];
    const float* Wv = (const float*)d_in[3];
    const float* Wo = (const float*)d_in[4];
    float* out = (float*)d_out;

    void* p;
    cudaGetSymbolAddress(&p, g_xpk);    uint2* xp = (uint2*)p;
    cudaGetSymbolAddress(&p, g_xmpk);   uint2* mp = (uint2*)p;
    cudaGetSymbolAddress(&p, g_wpk_hi); uint32_t* whi = (uint32_t*)p;
    cudaGetSymbolAddress(&p, g_wpk_lo); uint32_t* wlo = (uint32_t*)p;
    cudaGetSymbolAddress(&p, g_apk);    uint2* ap = (uint2*)p;
    cudaGetSymbolAddress(&p, g_qloc);   __half* qloc = (__half*)p;
    cudaGetSymbolAddress(&p, g_kbuf);   __half* kbuf = (__half*)p;
    cudaGetSymbolAddress(&p, g_vbuf);   float*  vbuf = (float*)p;

    cudaFuncSetAttribute(gemm_pk<0,1,1>, cudaFuncAttributeMaxDynamicSharedMemorySize, SMEM1);
    cudaFuncSetAttribute(gemm_pk<1,1,1>, cudaFuncAttributeMaxDynamicSharedMemorySize, SMEM1);
    cudaFuncSetAttribute(gemm_pk<0,0,2>, cudaFuncAttributeMaxDynamicSharedMemorySize, SMEM2);

    const int WSZ = C_ * C2_;

    prep_w_kernel<<<4 * WSZ / 256, 256>>>(Wq, Wk, Wv, Wo, whi, wlo);
    {
        dim3 g(HW_ / 1024, 64, B_);
        prep_x_kernel<<<g, 256>>>(x, xp, mp);
    }
    {   // Qloc = Wq * xmean  -> fp16  (single product: scores only)
        dim3 g(HW_ / NTT, C_ / MT, B_);
        gemm_pk<0,1,1><<<g, 256, SMEM1>>>(whi + 0 * WSZ, wlo + 0 * WSZ,
                                          nullptr, nullptr, mp, qloc, nullptr);
    }
    {   // K (fp16) and V (fp32) projections  (single product)
        dim3 g(HW_ / NTT, C_ / MT, B_ * V_ * 2);
        gemm_pk<1,1,1><<<g, 256, SMEM1>>>(whi + 1 * WSZ, wlo + 1 * WSZ,
                                          whi + 2 * WSZ, wlo + 2 * WSZ,
                                          xp, kbuf, vbuf);
    }
    attn_kernel<<<B_ * NH_ * (HW_ / 256), 256>>>(qloc, kbuf, vbuf, ap);
    {   // out = Wo * att  -> fp32  (2-product: final output)
        dim3 g(HW_ / NTT, C_ / MT, B_);
        gemm_pk<0,0,2><<<g, 256, SMEM2>>>(whi + 3 * WSZ, wlo + 3 * WSZ,
                                          nullptr, nullptr, ap, out, nullptr);
    }
}

// round 13
// speedup vs baseline: 2.5582x; 1.0293x over previous
#include <cuda_runtime.h>
#include <cuda_fp16.h>
#include <cstdint>
#include <math.h>

// ---------------------------------------------------------------------------
// Problem constants
// ---------------------------------------------------------------------------
#define B_   4
#define V_   6
#define C_   256
#define C2_  128
#define HW_  4096
#define NH_  8
#define DH_  32
#define CHW_ (C_ * HW_)

// GEMM tiling
#define MT   128
#define NTT  128
#define KB   32           // k chunk (16 pairs)
#define NKCH (C_ / KB)    // 8

// smem (u32 units): B pair-packed only: [sl(8)][p(128)] uint2, pitch 132
#define A_U    2048                       // fragment-ordered A stride per chunk (gmem)
#define BP2    132
#define B_U    (8 * BP2 * 2)              // 2112 u32
#define NSTG   4
#define SMEM_B4 (NSTG * B_U * 4)          // 33792 B

// X pair layout: per z, [kc(8)][sl(8)][p(4096)] uint2
#define XZ_U2  (64 * HW_)

// ---------------------------------------------------------------------------
// Scratch (device globals)
// ---------------------------------------------------------------------------
__device__ __align__(128) uint2    g_xpk [B_ * V_ * XZ_U2];
__device__ __align__(128) uint2    g_xmpk[B_ * XZ_U2];
__device__ __align__(128) uint32_t g_wpk [4 * C_ * C2_];     // fragment order (hi only)
__device__ __align__(128) uint2    g_apk [B_ * XZ_U2];
__device__ __align__(128) __half   g_qloc[B_ * CHW_];
__device__ __align__(128) __half   g_kbuf[B_ * V_ * CHW_];
__device__ __align__(128) __half   g_vbuf[B_ * V_ * CHW_];   // fp16 now

// ---------------------------------------------------------------------------
// Helpers
// ---------------------------------------------------------------------------
__device__ __forceinline__ uint32_t smem_u32(const void* p) {
    uint32_t a;
    asm("{ .reg .u64 t; cvta.to.shared.u64 t, %1; cvt.u32.u64 %0, t; }" : "=r"(a) : "l"(p));
    return a;
}
__device__ __forceinline__ uint32_t packhf(float e0, float e1) {
    return ((uint32_t)__half_as_ushort(__float2half_rn(e1)) << 16)
         | (uint32_t)__half_as_ushort(__float2half_rn(e0));
}
__device__ __forceinline__ void mma16816(float* c, const uint32_t* a,
                                         uint32_t b0, uint32_t b1) {
    asm volatile(
        "mma.sync.aligned.m16n8k16.row.col.f32.f16.f16.f32 "
        "{%0,%1,%2,%3}, {%4,%5,%6,%7}, {%8,%9}, {%0,%1,%2,%3};\n"
        : "+f"(c[0]), "+f"(c[1]), "+f"(c[2]), "+f"(c[3])
        : "r"(a[0]), "r"(a[1]), "r"(a[2]), "r"(a[3]), "r"(b0), "r"(b1));
}
__device__ __forceinline__ void cpasync16(uint32_t dst, const void* src) {
    asm volatile("cp.async.cg.shared.global [%0], [%1], 16;\n" :: "r"(dst), "l"(src));
}
#define CP_COMMIT() asm volatile("cp.async.commit_group;\n" ::: "memory")
#define CP_WAIT(n)  asm volatile("cp.async.wait_group %0;\n" :: "n"(n) : "memory")

// ---------------------------------------------------------------------------
// prep_w: pack weights (fp16 hi only) into MMA FRAGMENT ORDER.
//   [w][ot(2)][kc(8)][blk(8)][s(2)][lane(32)][j(4)]
// ---------------------------------------------------------------------------
__global__ void __launch_bounds__(256) prep_w_kernel(
    const float* __restrict__ Wq, const float* __restrict__ Wk,
    const float* __restrict__ Wv, const float* __restrict__ Wo,
    uint32_t* __restrict__ hi)
{
    const int i = blockIdx.x * 256 + threadIdx.x;
    const int w = i >> 15;
    const int r = i & 32767;
    const int j    = r & 3;
    const int lane = (r >> 2) & 31;
    const int s    = (r >> 7) & 1;
    const int blk  = (r >> 8) & 7;
    const int kc   = (r >> 11) & 7;
    const int ot   = (r >> 14) & 1;
    const int o  = ot * 128 + blk * 16 + (j & 1) * 8 + (lane >> 2);
    const int k2 = kc * 16 + s * 8 + (j >> 1) * 4 + (lane & 3);
    const float* src = (w == 0) ? Wq : (w == 1) ? Wk : (w == 2) ? Wv : Wo;
    const float2 f = *(const float2*)(src + o * C_ + k2 * 2);
    hi[i] = packhf(f.x, f.y);
}

// ---------------------------------------------------------------------------
// prep_x: fused view-mean + fp16 pack into PAIR layout (unchanged).
// ---------------------------------------------------------------------------
__global__ void __launch_bounds__(256) prep_x_kernel(
    const float* __restrict__ x,
    uint2* __restrict__ xp, uint2* __restrict__ mp)
{
    const int p  = blockIdx.x * 1024 + threadIdx.x * 4;
    const int sl = blockIdx.y & 7;
    const int kc = blockIdx.y >> 3;
    const int b  = blockIdx.z;
    const int s = sl >> 2, t = sl & 3;
    const int ca = (kc * 16 + s * 8 + t) * 2;

    float4 sea = make_float4(0,0,0,0), soa = sea, seb = sea, sob = sea;
#pragma unroll
    for (int v = 0; v < V_; ++v) {
        const float* base = x + ((size_t)((b * V_ + v) * C_) + ca) * HW_ + p;
        const float4 ea = *(const float4*)base;
        const float4 oa = *(const float4*)(base + HW_);
        const float4 eb = *(const float4*)(base + 8 * HW_);
        const float4 ob = *(const float4*)(base + 9 * HW_);
        sea.x += ea.x; sea.y += ea.y; sea.z += ea.z; sea.w += ea.w;
        soa.x += oa.x; soa.y += oa.y; soa.z += oa.z; soa.w += oa.w;
        seb.x += eb.x; seb.y += eb.y; seb.z += eb.z; seb.w += eb.w;
        sob.x += ob.x; sob.y += ob.y; sob.z += ob.z; sob.w += ob.w;
        uint2* dst = xp + ((size_t)(b * V_ + v) * 64 + blockIdx.y) * HW_ + p;
        dst[0] = make_uint2(packhf(ea.x, oa.x), packhf(eb.x, ob.x));
        dst[1] = make_uint2(packhf(ea.y, oa.y), packhf(eb.y, ob.y));
        dst[2] = make_uint2(packhf(ea.z, oa.z), packhf(eb.z, ob.z));
        dst[3] = make_uint2(packhf(ea.w, oa.w), packhf(eb.w, ob.w));
    }
    const float inv = 1.0f / 6.0f;
    uint2* dst = mp + ((size_t)b * 64 + blockIdx.y) * HW_ + p;
    dst[0] = make_uint2(packhf(sea.x * inv, soa.x * inv), packhf(seb.x * inv, sob.x * inv));
    dst[1] = make_uint2(packhf(sea.y * inv, soa.y * inv), packhf(seb.y * inv, sob.y * inv));
    dst[2] = make_uint2(packhf(sea.z * inv, soa.z * inv), packhf(seb.z * inv, sob.z * inv));
    dst[3] = make_uint2(packhf(sea.w * inv, soa.w * inv), packhf(seb.w * inv, sob.w * inv));
}

// ---------------------------------------------------------------------------
// HMMA GEMM, fp16 single-product: Y = Wh * Xh.
//   A fragments loaded via LDG (L2-resident, register double-buffer).
//   B pair-packed in smem, 4-stage cp.async, 1 barrier per chunk.
//   KV=1: z in [0,48): view=z>>1, sel=z&1; both outputs fp16.
//   KV=0: E16 selects output type (1 -> fp16, 0 -> fp32).
// ---------------------------------------------------------------------------
template <int KV, int E16>
__global__ void __launch_bounds__(256) gemm_pk(
    const uint32_t* __restrict__ Wf0, const uint32_t* __restrict__ Wf1,
    const uint2* __restrict__ Xh,
    void* __restrict__ Y0g, void* __restrict__ Y1g)
{
    extern __shared__ __align__(128) uint32_t smem[];
    const uint32_t sb = smem_u32(smem);

    const uint32_t* Wf;
    const uint2* Xhz;
    void* Yv;
    bool f16o;
    if (KV) {
        const int view = blockIdx.z >> 1;
        const int sel = blockIdx.z & 1;
        Wf = sel ? Wf1 : Wf0;
        Xhz = Xh + (size_t)view * XZ_U2;
        f16o = true;
        Yv = (void*)(((__half*)(sel ? Y1g : Y0g)) + (size_t)view * CHW_);
    } else {
        Wf = Wf0;
        Xhz = Xh + (size_t)blockIdx.z * XZ_U2;
        f16o = (E16 != 0);
        Yv = E16 ? (void*)((__half*)Y0g + (size_t)blockIdx.z * CHW_)
                 : (void*)((float*)Y0g + (size_t)blockIdx.z * CHW_);
    }

    const int tid = threadIdx.x;
    const int lane = tid & 31;
    const int wid = tid >> 5;
    const int p0 = blockIdx.x * NTT;
    const int ot = blockIdx.y;
    const int o0 = ot * MT;

    const int b_row = tid >> 5;
    const int b_pc  = (tid & 31) * 2;

    const int g = lane >> 2;
    const int t = lane & 3;
    const int mwb = (wid & 3) * 32;
    const int nwb = (wid >> 2) * 64;
    const int blk0 = (wid & 3) * 2;

    float acc[2][8][4];
#pragma unroll
    for (int mi = 0; mi < 2; ++mi)
#pragma unroll
        for (int ni = 0; ni < 8; ++ni)
#pragma unroll
            for (int j = 0; j < 4; ++j) acc[mi][ni][j] = 0.f;

    // B-only cp.async
    auto issueB = [&](int kc, int buf) {
        const uint32_t dBh = sb + buf * B_U * 4;
#pragma unroll
        for (int r = 0; r < 2; ++r) {
            const int pc = b_pc + r * 64;
            cpasync16(dBh + b_row * (BP2 * 8) + pc * 8,
                      Xhz + (size_t)(kc * 8 + b_row) * HW_ + p0 + pc);
        }
        CP_COMMIT();
    };

    // A via LDG (L2-resident, fragment-ordered), register double-buffer
    uint4 a_cur[2][2], a_nxt[2][2];   // [mi][s]
    auto ldA = [&](int kc, uint4 a[2][2]) {
        const uint32_t* base = Wf + (size_t)(ot * 8 + kc) * A_U;
#pragma unroll
        for (int mi = 0; mi < 2; ++mi)
#pragma unroll
            for (int s = 0; s < 2; ++s)
                a[mi][s] = *(const uint4*)(base + (((blk0 + mi) * 2 + s) * 32 + lane) * 4);
    };

    issueB(0, 0);
    issueB(1, 1);
    issueB(2, 2);
    ldA(0, a_cur);

    for (int kc = 0; kc < NKCH; ++kc) {
        if (kc <= NKCH - 3)      CP_WAIT(2);
        else if (kc == NKCH - 2) CP_WAIT(1);
        else                     CP_WAIT(0);
        __syncthreads();
        if (kc + 3 < NKCH) issueB(kc + 3, (kc + 3) & 3);
        if (kc + 1 < NKCH) ldA(kc + 1, a_nxt);

        const uint2* sB2 = (const uint2*)(smem + (kc & 3) * B_U);

#pragma unroll
        for (int s = 0; s < 2; ++s) {
            const int brow = (s * 4 + t) * BP2;
#pragma unroll
            for (int ni = 0; ni < 8; ++ni) {
                const int n0 = nwb + ni * 8 + g;
                const uint2 bv = sB2[brow + n0];
                mma16816(acc[0][ni], (const uint32_t*)&a_cur[0][s], bv.x, bv.y);
                mma16816(acc[1][ni], (const uint32_t*)&a_cur[1][s], bv.x, bv.y);
            }
        }
#pragma unroll
        for (int mi = 0; mi < 2; ++mi)
#pragma unroll
            for (int s = 0; s < 2; ++s)
                a_cur[mi][s] = a_nxt[mi][s];
    }

    // epilogue
    if (f16o) {
        __half* Yh = (__half*)Yv;
#pragma unroll
        for (int mi = 0; mi < 2; ++mi) {
            const int o = o0 + mwb + mi * 16 + g;
#pragma unroll
            for (int ni = 0; ni < 8; ++ni) {
                const int p = p0 + nwb + ni * 8 + t * 2;
                *(__half2*)(Yh + (size_t)o * HW_ + p) =
                    __floats2half2_rn(acc[mi][ni][0], acc[mi][ni][1]);
                *(__half2*)(Yh + (size_t)(o + 8) * HW_ + p) =
                    __floats2half2_rn(acc[mi][ni][2], acc[mi][ni][3]);
            }
        }
    } else {
        float* Y = (float*)Yv;
#pragma unroll
        for (int mi = 0; mi < 2; ++mi) {
            const int o = o0 + mwb + mi * 16 + g;
#pragma unroll
            for (int ni = 0; ni < 8; ++ni) {
                const int p = p0 + nwb + ni * 8 + t * 2;
                *(float2*)(Y + (size_t)o * HW_ + p) =
                    make_float2(acc[mi][ni][0], acc[mi][ni][1]);
                *(float2*)(Y + (size_t)(o + 8) * HW_ + p) =
                    make_float2(acc[mi][ni][2], acc[mi][ni][3]);
            }
        }
    }
}

// ---------------------------------------------------------------------------
// Per-pixel cross-view attention. Q,K,V all fp16 in; fp32 math; PAIR fp16 out.
// ---------------------------------------------------------------------------
__global__ void __launch_bounds__(256) attn_kernel(
    const __half* __restrict__ Q, const __half* __restrict__ K,
    const __half* __restrict__ Vv, uint2* __restrict__ Op)
{
    const int p = ((blockIdx.x & 15) << 8) + threadIdx.x;
    const int bh = blockIdx.x >> 4;
    const int b = bh >> 3;
    const int h = bh & 7;

    const size_t qbase = ((size_t)(b * C_ + h * DH_)) * HW_ + p;

    float q[DH_];
#pragma unroll
    for (int d = 0; d < DH_; ++d) q[d] = __half2float(Q[qbase + (size_t)d * HW_]);

    float s[V_];
#pragma unroll
    for (int v = 0; v < V_; ++v) {
        const size_t kb = ((size_t)((b * V_ + v) * C_ + h * DH_)) * HW_ + p;
        float dot = 0.f;
#pragma unroll
        for (int d = 0; d < DH_; ++d)
            dot += q[d] * __half2float(K[kb + (size_t)d * HW_]);
        s[v] = dot * 0.17677669529663687f;
    }
    float m = s[0];
#pragma unroll
    for (int v = 1; v < V_; ++v) m = fmaxf(m, s[v]);
    float sum = 0.f;
#pragma unroll
    for (int v = 0; v < V_; ++v) { s[v] = expf(s[v] - m); sum += s[v]; }
    const float invsum = 1.f / sum;

    float acc[DH_];
#pragma unroll
    for (int d = 0; d < DH_; ++d) acc[d] = 0.f;
#pragma unroll
    for (int v = 0; v < V_; ++v) {
        const float w = s[v] * invsum;
        const size_t vb = ((size_t)((b * V_ + v) * C_ + h * DH_)) * HW_ + p;
#pragma unroll
        for (int d = 0; d < DH_; ++d)
            acc[d] += w * __half2float(Vv[vb + (size_t)d * HW_]);
    }
#pragma unroll
    for (int sl = 0; sl < 8; ++sl) {
        const int d = (sl >> 2) * 8 + (sl & 3);
        Op[((size_t)(b * 8 + h) * 8 + sl) * HW_ + p] =
            make_uint2(packhf(acc[2 * d], acc[2 * d + 1]),
                       packhf(acc[2 * (d + 4)], acc[2 * (d + 4) + 1]));
    }
}

// ---------------------------------------------------------------------------
// kernel_launch
// ---------------------------------------------------------------------------
extern "C" void kernel_launch(void* const* d_in, const int* in_sizes, int n_in,
                              void* d_out, int out_size)
{
    const float* x  = (const float*)d_in[0];
    const float* Wq = (const float*)d_in[1];
    const float* Wk = (const float*)d_in[2];
    const float* Wv = (const float*)d_in[3];
    const float* Wo = (const float*)d_in[4];
    float* out = (float*)d_out;

    void* p;
    cudaGetSymbolAddress(&p, g_xpk);    uint2* xp = (uint2*)p;
    cudaGetSymbolAddress(&p, g_xmpk);   uint2* mp = (uint2*)p;
    cudaGetSymbolAddress(&p, g_wpk);    uint32_t* wpk = (uint32_t*)p;
    cudaGetSymbolAddress(&p, g_apk);    uint2* ap = (uint2*)p;
    cudaGetSymbolAddress(&p, g_qloc);   __half* qloc = (__half*)p;
    cudaGetSymbolAddress(&p, g_kbuf);   __half* kbuf = (__half*)p;
    cudaGetSymbolAddress(&p, g_vbuf);   __half* vbuf = (__half*)p;

    cudaFuncSetAttribute(gemm_pk<0,1>, cudaFuncAttributeMaxDynamicSharedMemorySize, SMEM_B4);
    cudaFuncSetAttribute(gemm_pk<1,1>, cudaFuncAttributeMaxDynamicSharedMemorySize, SMEM_B4);
    cudaFuncSetAttribute(gemm_pk<0,0>, cudaFuncAttributeMaxDynamicSharedMemorySize, SMEM_B4);

    const int WSZ = C_ * C2_;

    prep_w_kernel<<<4 * WSZ / 256, 256>>>(Wq, Wk, Wv, Wo, wpk);
    {
        dim3 g(HW_ / 1024, 64, B_);
        prep_x_kernel<<<g, 256>>>(x, xp, mp);
    }
    {   // Qloc = Wq * xmean  -> fp16
        dim3 g(HW_ / NTT, C_ / MT, B_);
        gemm_pk<0,1><<<g, 256, SMEM_B4>>>(wpk + 0 * WSZ, nullptr, mp, qloc, nullptr);
    }
    {   // K and V projections -> fp16
        dim3 g(HW_ / NTT, C_ / MT, B_ * V_ * 2);
        gemm_pk<1,1><<<g, 256, SMEM_B4>>>(wpk + 1 * WSZ, wpk + 2 * WSZ,
                                          xp, kbuf, vbuf);
    }
    attn_kernel<<<B_ * NH_ * (HW_ / 256), 256>>>(qloc, kbuf, vbuf, ap);
    {   // out = Wo * att  -> fp32
        dim3 g(HW_ / NTT, C_ / MT, B_);
        gemm_pk<0,0><<<g, 256, SMEM_B4>>>(wpk + 3 * WSZ, nullptr, ap, out, nullptr);
    }
}

// round 14
// speedup vs baseline: 2.7248x; 1.0651x over previous
#include <cuda_runtime.h>
#include <cuda_fp16.h>
#include <cstdint>
#include <math.h>

// ---------------------------------------------------------------------------
// Problem constants
// ---------------------------------------------------------------------------
#define B_   4
#define V_   6
#define C_   256
#define C2_  128
#define HW_  4096
#define NH_  8
#define DH_  32
#define CHW_ (C_ * HW_)

// GEMM tiling
#define MT   128
#define NTT  128          // p tile for single-output gemm
#define NTKV 64           // p tile for fused K+V gemm
#define KB   32           // k chunk (16 pairs)
#define NKCH (C_ / KB)    // 8

#define A_U    2048       // fragment-ordered A per chunk (u32)
// single-output gemm (Qloc / Wo): B pair-packed [sl(8)][p(128)] uint2, pitch 132
#define BP2    132
#define B_U    (8 * BP2 * 2)              // 2112 u32
#define NSTG   4
#define BUF1_U (A_U + B_U)                // 4160 (A + B)
#define SMEM1  (NSTG * BUF1_U * 4)        // 66560 B
// fused KV gemm: B [sl(8)][p(64)] uint2 pitch 68
#define BPK    68
#define BKV_U  (8 * BPK * 2)              // 1088 u32
#define BUFKV_U (2 * A_U + BKV_U)         // 5184
#define SMEMKV (NSTG * BUFKV_U * 4)       // 82944 B

// X pair layout: per z, [kc(8)][sl(8)][p(4096)] uint2
#define XZ_U2  (64 * HW_)

// ---------------------------------------------------------------------------
// Scratch (device globals)
// ---------------------------------------------------------------------------
__device__ __align__(128) uint2    g_xpk [B_ * V_ * XZ_U2];
__device__ __align__(128) uint2    g_xmpk[B_ * XZ_U2];
__device__ __align__(128) uint32_t g_wpk [4 * C_ * C2_];     // fragment order (fp16 hi)
__device__ __align__(128) uint2    g_apk [B_ * XZ_U2];
__device__ __align__(128) __half   g_qloc[B_ * CHW_];
__device__ __align__(128) __half   g_kbuf[B_ * V_ * CHW_];
__device__ __align__(128) __half   g_vbuf[B_ * V_ * CHW_];

// ---------------------------------------------------------------------------
// Helpers
// ---------------------------------------------------------------------------
__device__ __forceinline__ uint32_t smem_u32(const void* p) {
    uint32_t a;
    asm("{ .reg .u64 t; cvta.to.shared.u64 t, %1; cvt.u32.u64 %0, t; }" : "=r"(a) : "l"(p));
    return a;
}
__device__ __forceinline__ uint32_t packhf(float e0, float e1) {
    return ((uint32_t)__half_as_ushort(__float2half_rn(e1)) << 16)
         | (uint32_t)__half_as_ushort(__float2half_rn(e0));
}
__device__ __forceinline__ void mma16816(float* c, const uint32_t* a,
                                         uint32_t b0, uint32_t b1) {
    asm volatile(
        "mma.sync.aligned.m16n8k16.row.col.f32.f16.f16.f32 "
        "{%0,%1,%2,%3}, {%4,%5,%6,%7}, {%8,%9}, {%0,%1,%2,%3};\n"
        : "+f"(c[0]), "+f"(c[1]), "+f"(c[2]), "+f"(c[3])
        : "r"(a[0]), "r"(a[1]), "r"(a[2]), "r"(a[3]), "r"(b0), "r"(b1));
}
__device__ __forceinline__ void cpasync16(uint32_t dst, const void* src) {
    asm volatile("cp.async.cg.shared.global [%0], [%1], 16;\n" :: "r"(dst), "l"(src));
}
#define CP_COMMIT() asm volatile("cp.async.commit_group;\n" ::: "memory")
#define CP_WAIT(n)  asm volatile("cp.async.wait_group %0;\n" :: "n"(n) : "memory")

// ---------------------------------------------------------------------------
// prep_w: pack weights (fp16 hi) into MMA FRAGMENT ORDER.
//   [w][ot(2)][kc(8)][blk(8)][s(2)][lane(32)][j(4)]
// ---------------------------------------------------------------------------
__global__ void __launch_bounds__(256) prep_w_kernel(
    const float* __restrict__ Wq, const float* __restrict__ Wk,
    const float* __restrict__ Wv, const float* __restrict__ Wo,
    uint32_t* __restrict__ hi)
{
    const int i = blockIdx.x * 256 + threadIdx.x;
    const int w = i >> 15;
    const int r = i & 32767;
    const int j    = r & 3;
    const int lane = (r >> 2) & 31;
    const int s    = (r >> 7) & 1;
    const int blk  = (r >> 8) & 7;
    const int kc   = (r >> 11) & 7;
    const int ot   = (r >> 14) & 1;
    const int o  = ot * 128 + blk * 16 + (j & 1) * 8 + (lane >> 2);
    const int k2 = kc * 16 + s * 8 + (j >> 1) * 4 + (lane & 3);
    const float* src = (w == 0) ? Wq : (w == 1) ? Wk : (w == 2) ? Wv : Wo;
    const float2 f = *(const float2*)(src + o * C_ + k2 * 2);
    hi[i] = packhf(f.x, f.y);
}

// ---------------------------------------------------------------------------
// prep_x: fused view-mean + fp16 pack into PAIR layout (unchanged).
// ---------------------------------------------------------------------------
__global__ void __launch_bounds__(256) prep_x_kernel(
    const float* __restrict__ x,
    uint2* __restrict__ xp, uint2* __restrict__ mp)
{
    const int p  = blockIdx.x * 1024 + threadIdx.x * 4;
    const int sl = blockIdx.y & 7;
    const int kc = blockIdx.y >> 3;
    const int b  = blockIdx.z;
    const int s = sl >> 2, t = sl & 3;
    const int ca = (kc * 16 + s * 8 + t) * 2;

    float4 sea = make_float4(0,0,0,0), soa = sea, seb = sea, sob = sea;
#pragma unroll
    for (int v = 0; v < V_; ++v) {
        const float* base = x + ((size_t)((b * V_ + v) * C_) + ca) * HW_ + p;
        const float4 ea = *(const float4*)base;
        const float4 oa = *(const float4*)(base + HW_);
        const float4 eb = *(const float4*)(base + 8 * HW_);
        const float4 ob = *(const float4*)(base + 9 * HW_);
        sea.x += ea.x; sea.y += ea.y; sea.z += ea.z; sea.w += ea.w;
        soa.x += oa.x; soa.y += oa.y; soa.z += oa.z; soa.w += oa.w;
        seb.x += eb.x; seb.y += eb.y; seb.z += eb.z; seb.w += eb.w;
        sob.x += ob.x; sob.y += ob.y; sob.z += ob.z; sob.w += ob.w;
        uint2* dst = xp + ((size_t)(b * V_ + v) * 64 + blockIdx.y) * HW_ + p;
        dst[0] = make_uint2(packhf(ea.x, oa.x), packhf(eb.x, ob.x));
        dst[1] = make_uint2(packhf(ea.y, oa.y), packhf(eb.y, ob.y));
        dst[2] = make_uint2(packhf(ea.z, oa.z), packhf(eb.z, ob.z));
        dst[3] = make_uint2(packhf(ea.w, oa.w), packhf(eb.w, ob.w));
    }
    const float inv = 1.0f / 6.0f;
    uint2* dst = mp + ((size_t)b * 64 + blockIdx.y) * HW_ + p;
    dst[0] = make_uint2(packhf(sea.x * inv, soa.x * inv), packhf(seb.x * inv, sob.x * inv));
    dst[1] = make_uint2(packhf(sea.y * inv, soa.y * inv), packhf(seb.y * inv, sob.y * inv));
    dst[2] = make_uint2(packhf(sea.z * inv, soa.z * inv), packhf(seb.z * inv, sob.z * inv));
    dst[3] = make_uint2(packhf(sea.w * inv, soa.w * inv), packhf(seb.w * inv, sob.w * inv));
}

// ---------------------------------------------------------------------------
// FUSED K+V GEMM: one CTA computes K = Wk*X and V = Wv*X for a 128o x 64p tile.
//   A (both weights) in smem, fragment-ordered LDS.128; B pair LDS.64.
//   4-stage cp.async, 1 barrier per chunk. fp16 outputs.
// grid (HW/64, 2, B*V), 256 threads.
// ---------------------------------------------------------------------------
__global__ void __launch_bounds__(256) gemm_kv(
    const uint32_t* __restrict__ Wkf, const uint32_t* __restrict__ Wvf,
    const uint2* __restrict__ Xh,
    __half* __restrict__ Kg, __half* __restrict__ Vg)
{
    extern __shared__ __align__(128) uint32_t smem[];
    const uint32_t sb = smem_u32(smem);

    const int z = blockIdx.z;
    const uint2* Xhz = Xh + (size_t)z * XZ_U2;
    __half* Kout = Kg + (size_t)z * CHW_;
    __half* Vout = Vg + (size_t)z * CHW_;

    const int tid = threadIdx.x;
    const int lane = tid & 31;
    const int wid = tid >> 5;
    const int p0 = blockIdx.x * NTKV;
    const int ot = blockIdx.y;
    const int o0 = ot * MT;

    // cp.async B: one 16B per thread per chunk
    const int b_sl = tid >> 5;           // 0..7
    const int b_pc = (tid & 31) * 2;     // p offset (2 p per 16B)

    // mma fragment indices
    const int g = lane >> 2;
    const int t = lane & 3;
    const int mwb = (wid & 3) * 32;
    const int nwb = (wid >> 2) * 32;     // 2 n-groups x 32
    const int blk0 = (wid & 3) * 2;

    float accK[2][4][4], accV[2][4][4];
#pragma unroll
    for (int mi = 0; mi < 2; ++mi)
#pragma unroll
        for (int ni = 0; ni < 4; ++ni)
#pragma unroll
            for (int j = 0; j < 4; ++j) { accK[mi][ni][j] = 0.f; accV[mi][ni][j] = 0.f; }

    auto issue = [&](int kc, int buf) {
        const uint32_t base = sb + buf * BUFKV_U * 4;
        const size_t wsrc = (size_t)(ot * 8 + kc) * A_U;
#pragma unroll
        for (int r = 0; r < 2; ++r) {
            const uint32_t aoff = r * 1024 + tid * 4;
            cpasync16(base + aoff * 4, Wkf + wsrc + aoff);
            cpasync16(base + A_U * 4 + aoff * 4, Wvf + wsrc + aoff);
        }
        cpasync16(base + 2 * A_U * 4 + (b_sl * BPK + b_pc) * 8,
                  Xhz + (size_t)(kc * 8 + b_sl) * HW_ + p0 + b_pc);
        CP_COMMIT();
    };

    issue(0, 0);
    issue(1, 1);
    issue(2, 2);

    for (int kc = 0; kc < NKCH; ++kc) {
        if (kc <= NKCH - 3)      CP_WAIT(2);
        else if (kc == NKCH - 2) CP_WAIT(1);
        else                     CP_WAIT(0);
        __syncthreads();
        if (kc + 3 < NKCH) issue(kc + 3, (kc + 3) & 3);

        const uint32_t* bb = smem + (kc & 3) * BUFKV_U;
        const uint32_t* sAk = bb;
        const uint32_t* sAv = bb + A_U;
        const uint2* sB2 = (const uint2*)(bb + 2 * A_U);

#pragma unroll
        for (int s = 0; s < 2; ++s) {
            uint4 ak[2], av[2];
#pragma unroll
            for (int mi = 0; mi < 2; ++mi) {
                const uint32_t fo = (((blk0 + mi) * 2 + s) * 32 + lane) * 4;
                ak[mi] = *(const uint4*)&sAk[fo];
                av[mi] = *(const uint4*)&sAv[fo];
            }
            const int brow = (s * 4 + t) * BPK;
#pragma unroll
            for (int ni = 0; ni < 4; ++ni) {
                const uint2 bv = sB2[brow + nwb + ni * 8 + g];
                mma16816(accK[0][ni], (const uint32_t*)&ak[0], bv.x, bv.y);
                mma16816(accK[1][ni], (const uint32_t*)&ak[1], bv.x, bv.y);
                mma16816(accV[0][ni], (const uint32_t*)&av[0], bv.x, bv.y);
                mma16816(accV[1][ni], (const uint32_t*)&av[1], bv.x, bv.y);
            }
        }
    }

    // epilogue: both outputs fp16
#pragma unroll
    for (int mi = 0; mi < 2; ++mi) {
        const int o = o0 + mwb + mi * 16 + g;
#pragma unroll
        for (int ni = 0; ni < 4; ++ni) {
            const int p = p0 + nwb + ni * 8 + t * 2;
            *(__half2*)(Kout + (size_t)o * HW_ + p) =
                __floats2half2_rn(accK[mi][ni][0], accK[mi][ni][1]);
            *(__half2*)(Kout + (size_t)(o + 8) * HW_ + p) =
                __floats2half2_rn(accK[mi][ni][2], accK[mi][ni][3]);
            *(__half2*)(Vout + (size_t)o * HW_ + p) =
                __floats2half2_rn(accV[mi][ni][0], accV[mi][ni][1]);
            *(__half2*)(Vout + (size_t)(o + 8) * HW_ + p) =
                __floats2half2_rn(accV[mi][ni][2], accV[mi][ni][3]);
        }
    }
}

// ---------------------------------------------------------------------------
// Single-output GEMM (Qloc, Wo): A in smem fragment-ordered, B pair-packed.
//   Y = Wh * Xh, fp16 or fp32 output. 4-stage, 1 barrier per chunk.
// grid (HW/128, 2, B), 256 threads.
// ---------------------------------------------------------------------------
template <int E16>
__global__ void __launch_bounds__(256) gemm_pk(
    const uint32_t* __restrict__ Wf, const uint2* __restrict__ Xh,
    void* __restrict__ Yg)
{
    extern __shared__ __align__(128) uint32_t smem[];
    const uint32_t sb = smem_u32(smem);

    const uint2* Xhz = Xh + (size_t)blockIdx.z * XZ_U2;
    void* Yv = E16 ? (void*)((__half*)Yg + (size_t)blockIdx.z * CHW_)
                   : (void*)((float*)Yg + (size_t)blockIdx.z * CHW_);

    const int tid = threadIdx.x;
    const int lane = tid & 31;
    const int wid = tid >> 5;
    const int p0 = blockIdx.x * NTT;
    const int ot = blockIdx.y;
    const int o0 = ot * MT;

    const int b_row = tid >> 5;
    const int b_pc  = (tid & 31) * 2;

    const int g = lane >> 2;
    const int t = lane & 3;
    const int mwb = (wid & 3) * 32;
    const int nwb = (wid >> 2) * 64;
    const int blk0 = (wid & 3) * 2;

    float acc[2][8][4];
#pragma unroll
    for (int mi = 0; mi < 2; ++mi)
#pragma unroll
        for (int ni = 0; ni < 8; ++ni)
#pragma unroll
            for (int j = 0; j < 4; ++j) acc[mi][ni][j] = 0.f;

    auto issue = [&](int kc, int buf) {
        const uint32_t base = sb + buf * BUF1_U * 4;
        const size_t wsrc = (size_t)(ot * 8 + kc) * A_U;
#pragma unroll
        for (int r = 0; r < 2; ++r) {
            const uint32_t aoff = r * 1024 + tid * 4;
            cpasync16(base + aoff * 4, Wf + wsrc + aoff);
            const int pc = b_pc + r * 64;
            cpasync16(base + A_U * 4 + b_row * (BP2 * 8) + pc * 8,
                      Xhz + (size_t)(kc * 8 + b_row) * HW_ + p0 + pc);
        }
        CP_COMMIT();
    };

    issue(0, 0);
    issue(1, 1);
    issue(2, 2);

    for (int kc = 0; kc < NKCH; ++kc) {
        if (kc <= NKCH - 3)      CP_WAIT(2);
        else if (kc == NKCH - 2) CP_WAIT(1);
        else                     CP_WAIT(0);
        __syncthreads();
        if (kc + 3 < NKCH) issue(kc + 3, (kc + 3) & 3);

        const uint32_t* bb = smem + (kc & 3) * BUF1_U;
        const uint32_t* sAh = bb;
        const uint2* sB2 = (const uint2*)(bb + A_U);

#pragma unroll
        for (int s = 0; s < 2; ++s) {
            uint4 ah[2];
#pragma unroll
            for (int mi = 0; mi < 2; ++mi) {
                const uint32_t fo = (((blk0 + mi) * 2 + s) * 32 + lane) * 4;
                ah[mi] = *(const uint4*)&sAh[fo];
            }
            const int brow = (s * 4 + t) * BP2;
#pragma unroll
            for (int ni = 0; ni < 8; ++ni) {
                const uint2 bv = sB2[brow + nwb + ni * 8 + g];
                mma16816(acc[0][ni], (const uint32_t*)&ah[0], bv.x, bv.y);
                mma16816(acc[1][ni], (const uint32_t*)&ah[1], bv.x, bv.y);
            }
        }
    }

    if (E16) {
        __half* Yh = (__half*)Yv;
#pragma unroll
        for (int mi = 0; mi < 2; ++mi) {
            const int o = o0 + mwb + mi * 16 + g;
#pragma unroll
            for (int ni = 0; ni < 8; ++ni) {
                const int p = p0 + nwb + ni * 8 + t * 2;
                *(__half2*)(Yh + (size_t)o * HW_ + p) =
                    __floats2half2_rn(acc[mi][ni][0], acc[mi][ni][1]);
                *(__half2*)(Yh + (size_t)(o + 8) * HW_ + p) =
                    __floats2half2_rn(acc[mi][ni][2], acc[mi][ni][3]);
            }
        }
    } else {
        float* Y = (float*)Yv;
#pragma unroll
        for (int mi = 0; mi < 2; ++mi) {
            const int o = o0 + mwb + mi * 16 + g;
#pragma unroll
            for (int ni = 0; ni < 8; ++ni) {
                const int p = p0 + nwb + ni * 8 + t * 2;
                *(float2*)(Y + (size_t)o * HW_ + p) =
                    make_float2(acc[mi][ni][0], acc[mi][ni][1]);
                *(float2*)(Y + (size_t)(o + 8) * HW_ + p) =
                    make_float2(acc[mi][ni][2], acc[mi][ni][3]);
            }
        }
    }
}

// ---------------------------------------------------------------------------
// Per-pixel cross-view attention. Q,K,V all fp16 in; fp32 math; PAIR fp16 out.
// ---------------------------------------------------------------------------
__global__ void __launch_bounds__(256) attn_kernel(
    const __half* __restrict__ Q, const __half* __restrict__ K,
    const __half* __restrict__ Vv, uint2* __restrict__ Op)
{
    const int p = ((blockIdx.x & 15) << 8) + threadIdx.x;
    const int bh = blockIdx.x >> 4;
    const int b = bh >> 3;
    const int h = bh & 7;

    const size_t qbase = ((size_t)(b * C_ + h * DH_)) * HW_ + p;

    float q[DH_];
#pragma unroll
    for (int d = 0; d < DH_; ++d) q[d] = __half2float(Q[qbase + (size_t)d * HW_]);

    float s[V_];
#pragma unroll
    for (int v = 0; v < V_; ++v) {
        const size_t kb = ((size_t)((b * V_ + v) * C_ + h * DH_)) * HW_ + p;
        float dot = 0.f;
#pragma unroll
        for (int d = 0; d < DH_; ++d)
            dot += q[d] * __half2float(K[kb + (size_t)d * HW_]);
        s[v] = dot * 0.17677669529663687f;
    }
    float m = s[0];
#pragma unroll
    for (int v = 1; v < V_; ++v) m = fmaxf(m, s[v]);
    float sum = 0.f;
#pragma unroll
    for (int v = 0; v < V_; ++v) { s[v] = expf(s[v] - m); sum += s[v]; }
    const float invsum = 1.f / sum;

    float acc[DH_];
#pragma unroll
    for (int d = 0; d < DH_; ++d) acc[d] = 0.f;
#pragma unroll
    for (int v = 0; v < V_; ++v) {
        const float w = s[v] * invsum;
        const size_t vb = ((size_t)((b * V_ + v) * C_ + h * DH_)) * HW_ + p;
#pragma unroll
        for (int d = 0; d < DH_; ++d)
            acc[d] += w * __half2float(Vv[vb + (size_t)d * HW_]);
    }
#pragma unroll
    for (int sl = 0; sl < 8; ++sl) {
        const int d = (sl >> 2) * 8 + (sl & 3);
        Op[((size_t)(b * 8 + h) * 8 + sl) * HW_ + p] =
            make_uint2(packhf(acc[2 * d], acc[2 * d + 1]),
                       packhf(acc[2 * (d + 4)], acc[2 * (d + 4) + 1]));
    }
}

// ---------------------------------------------------------------------------
// kernel_launch
// ---------------------------------------------------------------------------
extern "C" void kernel_launch(void* const* d_in, const int* in_sizes, int n_in,
                              void* d_out, int out_size)
{
    const float* x  = (const float*)d_in[0];
    const float* Wq = (const float*)d_in[1];
    const float* Wk = (const float*)d_in[2];
    const float* Wv = (const float*)d_in[3];
    const float* Wo = (const float*)d_in[4];
    float* out = (float*)d_out;

    void* p;
    cudaGetSymbolAddress(&p, g_xpk);    uint2* xp = (uint2*)p;
    cudaGetSymbolAddress(&p, g_xmpk);   uint2* mp = (uint2*)p;
    cudaGetSymbolAddress(&p, g_wpk);    uint32_t* wpk = (uint32_t*)p;
    cudaGetSymbolAddress(&p, g_apk);    uint2* ap = (uint2*)p;
    cudaGetSymbolAddress(&p, g_qloc);   __half* qloc = (__half*)p;
    cudaGetSymbolAddress(&p, g_kbuf);   __half* kbuf = (__half*)p;
    cudaGetSymbolAddress(&p, g_vbuf);   __half* vbuf = (__half*)p;

    cudaFuncSetAttribute(gemm_pk<1>, cudaFuncAttributeMaxDynamicSharedMemorySize, SMEM1);
    cudaFuncSetAttribute(gemm_pk<0>, cudaFuncAttributeMaxDynamicSharedMemorySize, SMEM1);
    cudaFuncSetAttribute(gemm_kv,    cudaFuncAttributeMaxDynamicSharedMemorySize, SMEMKV);

    const int WSZ = C_ * C2_;

    prep_w_kernel<<<4 * WSZ / 256, 256>>>(Wq, Wk, Wv, Wo, wpk);
    {
        dim3 g(HW_ / 1024, 64, B_);
        prep_x_kernel<<<g, 256>>>(x, xp, mp);
    }
    {   // Qloc = Wq * xmean  -> fp16
        dim3 g(HW_ / NTT, C_ / MT, B_);
        gemm_pk<1><<<g, 256, SMEM1>>>(wpk + 0 * WSZ, mp, qloc);
    }
    {   // fused K + V projections -> fp16
        dim3 g(HW_ / NTKV, C_ / MT, B_ * V_);
        gemm_kv<<<g, 256, SMEMKV>>>(wpk + 1 * WSZ, wpk + 2 * WSZ, xp, kbuf, vbuf);
    }
    attn_kernel<<<B_ * NH_ * (HW_ / 256), 256>>>(qloc, kbuf, vbuf, ap);
    {   // out = Wo * att  -> fp32
        dim3 g(HW_ / NTT, C_ / MT, B_);
        gemm_pk<0><<<g, 256, SMEM1>>>(wpk + 3 * WSZ, ap, out);
    }
}